// round 6
// baseline (speedup 1.0000x reference)
#include <cuda_runtime.h>
#include <math.h>

#define EPS 1e-5f

// ---------------- scratch (allocation is forbidden -> __device__ globals) --
__device__ float g_x1[4u * 64u * 128u * 128u];     // gelu(conv1(x))        16.8 MB
__device__ float g_skip[4u * 64u * 128u * 128u];   // bn(mapping(x))        16.8 MB
__device__ float g_w[4u * 196u * 128u * 128u];     // involution weights    51.4 MB

__device__ __forceinline__ float gelu1(float v) {
    return 0.5f * v * (1.0f + erff(v * 0.70710678118654752440f));
}

// ===========================================================================
// Kernel 1 (pointwise): per pixel
//   x1   = gelu(w1 @ x)                       -> g_x1
//   r    = relu(bn_r(wr @ x1))
//   wv   = ws @ r + bs  (196 values)          -> g_w
//   skip = bn_m(wm @ x + bmap)                -> g_skip
// ===========================================================================
__global__ void __launch_bounds__(256) k_pre(
    const float* __restrict__ x,  const float* __restrict__ w1,
    const float* __restrict__ wr, const float* __restrict__ gr,
    const float* __restrict__ br, const float* __restrict__ mr,
    const float* __restrict__ vr, const float* __restrict__ ws,
    const float* __restrict__ bs, const float* __restrict__ wm,
    const float* __restrict__ bmap, const float* __restrict__ gm,
    const float* __restrict__ betam, const float* __restrict__ mm,
    const float* __restrict__ vm)
{
    __shared__ __align__(16) float w1t[2048];   // [ci][o]
    __shared__ __align__(16) float wmt[2048];   // [ci][o], bn-folded
    __shared__ __align__(16) float wrt[1024];   // [c][j]
    __shared__ __align__(16) float wst[3136];   // [j][k]
    __shared__ float tmv[64], srv[16], trv[16], bsv[196];

    const int tid = threadIdx.x;
    for (int i = tid; i < 2048; i += 256) {
        int ci = i >> 6, o = i & 63;
        w1t[i] = w1[o * 32 + ci];
        float s = gm[o] * rsqrtf(vm[o] + EPS);
        wmt[i] = wm[o * 32 + ci] * s;
    }
    if (tid < 64) {
        float s = gm[tid] * rsqrtf(vm[tid] + EPS);
        tmv[tid] = s * bmap[tid] + betam[tid] - mm[tid] * s;
    }
    for (int i = tid; i < 1024; i += 256) { int c = i >> 4, j = i & 15; wrt[i] = wr[j * 64 + c]; }
    if (tid < 16) {
        float s = gr[tid] * rsqrtf(vr[tid] + EPS);
        srv[tid] = s; trv[tid] = br[tid] - mr[tid] * s;
    }
    for (int i = tid; i < 3136; i += 256) { int j = i / 196, k = i - j * 196; wst[i] = ws[k * 16 + j]; }
    if (tid < 196) bsv[tid] = bs[tid];
    __syncthreads();

    const int pixel = blockIdx.x * 256 + tid;
    const int b = pixel >> 14, pix = pixel & 16383;
    const float* xb = x + ((size_t)b << 19) + pix;   // b*32*16384

    float xv[32];
#pragma unroll
    for (int ci = 0; ci < 32; ci++) xv[ci] = __ldg(xb + ((size_t)ci << 14));

    // ---- conv1 + gelu ----
    float acc[64];
#pragma unroll
    for (int o = 0; o < 64; o++) acc[o] = 0.f;
#pragma unroll
    for (int ci = 0; ci < 32; ci++) {
        float xc = xv[ci];
        const float4* wp = (const float4*)(w1t + ci * 64);
#pragma unroll
        for (int o4 = 0; o4 < 16; o4++) {
            float4 w = wp[o4];
            acc[o4 * 4 + 0] += w.x * xc; acc[o4 * 4 + 1] += w.y * xc;
            acc[o4 * 4 + 2] += w.z * xc; acc[o4 * 4 + 3] += w.w * xc;
        }
    }
    float* x1o = g_x1 + ((size_t)b << 20) + pix;
#pragma unroll
    for (int o = 0; o < 64; o++) { acc[o] = gelu1(acc[o]); x1o[(size_t)o << 14] = acc[o]; }

    // ---- reduce + bn + relu ----
    float r[16];
#pragma unroll
    for (int j = 0; j < 16; j++) r[j] = 0.f;
#pragma unroll
    for (int c = 0; c < 64; c++) {
        float xc = acc[c];
        const float4* wp = (const float4*)(wrt + c * 16);
#pragma unroll
        for (int j4 = 0; j4 < 4; j4++) {
            float4 w = wp[j4];
            r[j4 * 4 + 0] += w.x * xc; r[j4 * 4 + 1] += w.y * xc;
            r[j4 * 4 + 2] += w.z * xc; r[j4 * 4 + 3] += w.w * xc;
        }
    }
#pragma unroll
    for (int j = 0; j < 16; j++) r[j] = fmaxf(srv[j] * r[j] + trv[j], 0.f);

    // ---- mapping skip (bn folded) ----
#pragma unroll
    for (int o = 0; o < 64; o++) acc[o] = tmv[o];
#pragma unroll
    for (int ci = 0; ci < 32; ci++) {
        float xc = xv[ci];
        const float4* wp = (const float4*)(wmt + ci * 64);
#pragma unroll
        for (int o4 = 0; o4 < 16; o4++) {
            float4 w = wp[o4];
            acc[o4 * 4 + 0] += w.x * xc; acc[o4 * 4 + 1] += w.y * xc;
            acc[o4 * 4 + 2] += w.z * xc; acc[o4 * 4 + 3] += w.w * xc;
        }
    }
    float* sko = g_skip + ((size_t)b << 20) + pix;
#pragma unroll
    for (int o = 0; o < 64; o++) sko[(size_t)o << 14] = acc[o];

    // ---- span: wv[196] = ws @ r + bs (4 chunks of 49) ----
    float* wvo = g_w + (((size_t)b * 196) << 14) + pix;
#pragma unroll
    for (int chunk = 0; chunk < 4; chunk++) {
        float wa[49];
#pragma unroll
        for (int k = 0; k < 49; k++) wa[k] = bsv[chunk * 49 + k];
#pragma unroll
        for (int j = 0; j < 16; j++) {
            float rj = r[j];
            const float* wp = wst + j * 196 + chunk * 49;
#pragma unroll
            for (int k = 0; k < 49; k++) wa[k] += wp[k] * rj;
        }
#pragma unroll
        for (int k = 0; k < 49; k++) wvo[((size_t)(chunk * 49 + k)) << 14] = wa[k];
    }
}

// ===========================================================================
// Kernel 2: involution + BN1 + GELU + conv2(BN2 folded) + skip + GELU
// One CTA per 16x8 spatial tile. thread = (pixel 0..127, channel-half 0..1).
// ===========================================================================
#define TW 16
#define TH 8
#define HW 22
#define HH 14
#define HP 308           // HW*HH halo pixels
#define CSTR 68          // smem channel stride (floats); stride-68 => conflict-free LDS.128
#define X1S_FLOATS (HP * CSTR)                  // 20944
#define W2S_OFF    X1S_FLOATS                   // 20944
#define S1_OFF     (W2S_OFF + 4096)             // 25040
#define T1_OFF     (S1_OFF + 64)
#define T2_OFF     (T1_OFF + 64)
#define SMEMB_FLOATS (T2_OFF + 64)              // 25232
#define SMEMB_BYTES  (SMEMB_FLOATS * 4)         // 100928

extern __shared__ __align__(16) float smem[];

__global__ void __launch_bounds__(256) k_main(
    const float* __restrict__ g1, const float* __restrict__ b1,
    const float* __restrict__ m1, const float* __restrict__ v1,
    const float* __restrict__ w2, const float* __restrict__ g2,
    const float* __restrict__ b2, const float* __restrict__ m2,
    const float* __restrict__ v2, float* __restrict__ out)
{
    float* x1s = smem;                 // halo tile, later reused as y exchange
    float* w2s = smem + W2S_OFF;       // [c][o], bn2 scale folded
    float* s1v = smem + S1_OFF;
    float* t1v = smem + T1_OFF;
    float* t2v = smem + T2_OFF;

    const int tid = threadIdx.x;
    const int b = blockIdx.z;
    const int tx0 = blockIdx.x * TW, ty0 = blockIdx.y * TH;

    for (int i = tid; i < 4096; i += 256) {
        int c = i >> 6, o = i & 63;
        float s2 = g2[o] * rsqrtf(v2[o] + EPS);
        w2s[i] = w2[o * 64 + c] * s2;
    }
    if (tid < 64) {
        float s1 = g1[tid] * rsqrtf(v1[tid] + EPS);
        s1v[tid] = s1; t1v[tid] = b1[tid] - m1[tid] * s1;
        float s2 = g2[tid] * rsqrtf(v2[tid] + EPS);
        t2v[tid] = b2[tid] - m2[tid] * s2;
    }

    // load x1 halo (zero-padded), smem layout [halo_pixel][channel] stride CSTR
    const float* x1b = g_x1 + ((size_t)b << 20);
    for (int i = tid; i < HP * 64; i += 256) {
        int c = i / HP, hp = i - c * HP;
        int hy = hp / HW, hx = hp - hy * HW;
        int gy = ty0 - 3 + hy, gx = tx0 - 3 + hx;
        float v = 0.f;
        if (gy >= 0 && gy < 128 && gx >= 0 && gx < 128)
            v = __ldg(x1b + (((size_t)c) << 14) + (gy << 7) + gx);
        x1s[hp * CSTR + c] = v;
    }
    __syncthreads();

    const int p = tid & 127, half = tid >> 7;
    const int py = p >> 4, px = p & 15;
    const int gy = ty0 + py, gx = tx0 + px;
    const int pix = (gy << 7) + gx;

    // ---- involution (2 groups of 16 channels per thread) + BN1 + GELU ----
    float y[32];
    const float* wvb = g_w + (((size_t)b * 196) << 14) + pix;
#pragma unroll
    for (int gi = 0; gi < 2; gi++) {
        const int g = half * 2 + gi;
        float wq[49];
#pragma unroll
        for (int k = 0; k < 49; k++) wq[k] = __ldg(wvb + (((size_t)(g * 49 + k)) << 14));
        float acc[16];
#pragma unroll
        for (int c = 0; c < 16; c++) acc[c] = 0.f;
#pragma unroll
        for (int di = 0; di < 7; di++) {
#pragma unroll
            for (int dj = 0; dj < 7; dj++) {
                float kw = wq[di * 7 + dj];
                const float4* xp = (const float4*)(x1s + ((py + di) * HW + (px + dj)) * CSTR + g * 16);
#pragma unroll
                for (int c4 = 0; c4 < 4; c4++) {
                    float4 xv = xp[c4];
                    acc[c4 * 4 + 0] += kw * xv.x; acc[c4 * 4 + 1] += kw * xv.y;
                    acc[c4 * 4 + 2] += kw * xv.z; acc[c4 * 4 + 3] += kw * xv.w;
                }
            }
        }
#pragma unroll
        for (int c = 0; c < 16; c++) {
            int ch = g * 16 + c;
            y[gi * 16 + c] = gelu1(s1v[ch] * acc[c] + t1v[ch]);
        }
    }

    // ---- exchange y through smem (reuse halo buffer) ----
    __syncthreads();
    const int ch0 = half * 32;
#pragma unroll
    for (int c = 0; c < 32; c++) x1s[p * CSTR + ch0 + c] = y[c];
    __syncthreads();

    // ---- conv2 (bn2 folded) + skip + gelu ----
    float acc2[32];
#pragma unroll
    for (int o = 0; o < 32; o++) acc2[o] = t2v[ch0 + o];
    const float4* yp = (const float4*)(x1s + p * CSTR);
#pragma unroll
    for (int c4 = 0; c4 < 16; c4++) {
        float4 yv = yp[c4];
        float ya[4] = { yv.x, yv.y, yv.z, yv.w };
#pragma unroll
        for (int cc = 0; cc < 4; cc++) {
            float yc = ya[cc];
            const float4* wp = (const float4*)(w2s + (c4 * 4 + cc) * 64 + ch0);
#pragma unroll
            for (int o4 = 0; o4 < 8; o4++) {
                float4 w = wp[o4];
                acc2[o4 * 4 + 0] += w.x * yc; acc2[o4 * 4 + 1] += w.y * yc;
                acc2[o4 * 4 + 2] += w.z * yc; acc2[o4 * 4 + 3] += w.w * yc;
            }
        }
    }
    const float* skb = g_skip + ((size_t)b << 20) + pix;
    float* ob = out + ((size_t)b << 20) + pix;
#pragma unroll
    for (int o = 0; o < 32; o++) {
        float v = acc2[o] + skb[((size_t)(ch0 + o)) << 14];
        ob[((size_t)(ch0 + o)) << 14] = gelu1(v);
    }
}

// ===========================================================================
// Launch. Input order (metadata): x w1 wr gr br mr vr ws bs g1 b1 m1 v1
//                                 w2 g2 b2 m2 v2 wm bmap gm betam mm vm
// ===========================================================================
extern "C" void kernel_launch(void* const* d_in, const int* in_sizes, int n_in,
                              void* d_out, int out_size)
{
    (void)in_sizes; (void)n_in; (void)out_size;
    const float* x     = (const float*)d_in[0];
    const float* w1    = (const float*)d_in[1];
    const float* wr    = (const float*)d_in[2];
    const float* gr    = (const float*)d_in[3];
    const float* br    = (const float*)d_in[4];
    const float* mr    = (const float*)d_in[5];
    const float* vr    = (const float*)d_in[6];
    const float* ws    = (const float*)d_in[7];
    const float* bs    = (const float*)d_in[8];
    const float* g1    = (const float*)d_in[9];
    const float* b1    = (const float*)d_in[10];
    const float* m1    = (const float*)d_in[11];
    const float* v1    = (const float*)d_in[12];
    const float* w2    = (const float*)d_in[13];
    const float* g2    = (const float*)d_in[14];
    const float* b2    = (const float*)d_in[15];
    const float* m2    = (const float*)d_in[16];
    const float* v2    = (const float*)d_in[17];
    const float* wm    = (const float*)d_in[18];
    const float* bmap  = (const float*)d_in[19];
    const float* gm    = (const float*)d_in[20];
    const float* betam = (const float*)d_in[21];
    const float* mm    = (const float*)d_in[22];
    const float* vm    = (const float*)d_in[23];
    float* out = (float*)d_out;

    // Not a stream op; safe under graph capture. Idempotent.
    cudaFuncSetAttribute(k_main, cudaFuncAttributeMaxDynamicSharedMemorySize, SMEMB_BYTES);

    k_pre<<<256, 256>>>(x, w1, wr, gr, br, mr, vr, ws, bs,
                        wm, bmap, gm, betam, mm, vm);
    k_main<<<dim3(128 / TW, 128 / TH, 4), 256, SMEMB_BYTES>>>(
        g1, b1, m1, v1, w2, g2, b2, m2, v2, out);
}

// round 8
// speedup vs baseline: 1.1488x; 1.1488x over previous
#include <cuda_runtime.h>
#include <math.h>

#define EPS 1e-5f
typedef unsigned long long u64;

// ---------------- scratch (allocation forbidden -> __device__ globals) ----
__device__ float g_x1[4u * 64u * 128u * 128u];     // gelu(conv1(x))
__device__ float g_skip[4u * 64u * 128u * 128u];   // bn(mapping(x))
__device__ float g_w[4u * 196u * 128u * 128u];     // involution weights

// ---------------- f32x2 helpers ----------------
__device__ __forceinline__ u64 pack2(float a, float b) {
    u64 r; asm("mov.b64 %0,{%1,%2};" : "=l"(r) : "f"(a), "f"(b)); return r;
}
__device__ __forceinline__ void unpack2(u64 v, float &a, float &b) {
    asm("mov.b64 {%0,%1},%2;" : "=f"(a), "=f"(b) : "l"(v));
}
__device__ __forceinline__ u64 fma2(u64 a, u64 b, u64 c) {
    u64 d; asm("fma.rn.f32x2 %0,%1,%2,%3;" : "=l"(d) : "l"(a), "l"(b), "l"(c)); return d;
}
__device__ __forceinline__ float gelu1(float v) {
    return 0.5f * v * (1.0f + erff(v * 0.70710678118654752440f));
}

// ===========================================================================
// Kernel 1: per pixel-PAIR (2 adjacent pixels in one f32x2 lane)
//   x1 = gelu(w1@x); r = relu(bn(wr@x1)); g_w = ws@r+bs; g_skip = bn(wm@x+b)
// f32x2 lanes = PIXEL pairs -> weights duplicated ([w,w]) so LDS.128 yields
// two ready fma2 operands.
// ===========================================================================
#define KP_W1D 0        // 4096   [ci][o dup]
#define KP_WMD 4096     // 4096   [ci][o dup] (bn folded)
#define KP_WRD 8192     // 2048   [c][j dup]
#define KP_WSD 10240    // 6272   [j][k dup]
#define KP_TMD 16512    // 128    [o dup]  skip bias
#define KP_BSD 16640    // 392    [k dup]  span bias
#define KP_SRV 17032    // 16
#define KP_TRV 17048    // 16
#define KP_FLOATS 17064
#define KP_BYTES (KP_FLOATS * 4)

extern __shared__ __align__(16) float smem[];

__global__ void __launch_bounds__(128) k_pre(
    const float* __restrict__ x,  const float* __restrict__ w1,
    const float* __restrict__ wr, const float* __restrict__ gr,
    const float* __restrict__ br, const float* __restrict__ mr,
    const float* __restrict__ vr, const float* __restrict__ ws,
    const float* __restrict__ bs, const float* __restrict__ wm,
    const float* __restrict__ bmap, const float* __restrict__ gm,
    const float* __restrict__ betam, const float* __restrict__ mm,
    const float* __restrict__ vm)
{
    float* w1d = smem + KP_W1D;
    float* wmd = smem + KP_WMD;
    float* wrd = smem + KP_WRD;
    float* wsd = smem + KP_WSD;
    float* tmd = smem + KP_TMD;
    float* bsd = smem + KP_BSD;
    float* srv = smem + KP_SRV;
    float* trv = smem + KP_TRV;

    const int tid = threadIdx.x;
    for (int i = tid; i < 2048; i += 128) {
        int ci = i >> 6, o = i & 63;
        float v = w1[o * 32 + ci];
        w1d[ci * 128 + 2 * o] = v; w1d[ci * 128 + 2 * o + 1] = v;
        float s = gm[o] * rsqrtf(vm[o] + EPS);
        float v2 = wm[o * 32 + ci] * s;
        wmd[ci * 128 + 2 * o] = v2; wmd[ci * 128 + 2 * o + 1] = v2;
    }
    for (int i = tid; i < 1024; i += 128) {
        int c = i >> 4, j = i & 15;
        float v = wr[j * 64 + c];
        wrd[c * 32 + 2 * j] = v; wrd[c * 32 + 2 * j + 1] = v;
    }
    for (int i = tid; i < 3136; i += 128) {
        int j = i / 196, k = i - j * 196;
        float v = ws[k * 16 + j];
        wsd[j * 392 + 2 * k] = v; wsd[j * 392 + 2 * k + 1] = v;
    }
    if (tid < 64) {
        float s = gm[tid] * rsqrtf(vm[tid] + EPS);
        float t = s * bmap[tid] + betam[tid] - mm[tid] * s;
        tmd[2 * tid] = t; tmd[2 * tid + 1] = t;
    }
    if (tid < 16) {
        float s = gr[tid] * rsqrtf(vr[tid] + EPS);
        srv[tid] = s; trv[tid] = br[tid] - mr[tid] * s;
    }
    for (int i = tid; i < 196; i += 128) {
        float v = bs[i]; bsd[2 * i] = v; bsd[2 * i + 1] = v;
    }
    __syncthreads();

    const int pp = blockIdx.x * 128 + tid;          // pair id, 32768 total
    const int p0 = pp << 1;
    const int b = p0 >> 14, pix = p0 & 16383;
    const float* xb = x + ((size_t)b << 19) + pix;

    u64 xv[32];
#pragma unroll
    for (int ci = 0; ci < 32; ci++) xv[ci] = *(const u64*)(xb + ((size_t)ci << 14));

    // ---- conv1 + gelu (+ fused reduce accumulation) ----
    u64 r[16];
#pragma unroll
    for (int j = 0; j < 16; j++) r[j] = 0ull;
    float* x1o = g_x1 + ((size_t)b << 20) + pix;
#pragma unroll
    for (int ob = 0; ob < 4; ob++) {
        u64 acc[16];
#pragma unroll
        for (int q = 0; q < 16; q++) acc[q] = 0ull;
#pragma unroll
        for (int ci = 0; ci < 32; ci++) {
            const ulonglong2* wp = (const ulonglong2*)(w1d + ci * 128 + ob * 32);
            u64 xc = xv[ci];
#pragma unroll
            for (int q = 0; q < 8; q++) {
                ulonglong2 w = wp[q];
                acc[2 * q]     = fma2(w.x, xc, acc[2 * q]);
                acc[2 * q + 1] = fma2(w.y, xc, acc[2 * q + 1]);
            }
        }
#pragma unroll
        for (int lc = 0; lc < 16; lc++) {
            int c = ob * 16 + lc;
            float a0, a1; unpack2(acc[lc], a0, a1);
            u64 x1p = pack2(gelu1(a0), gelu1(a1));
            *(u64*)(x1o + ((size_t)c << 14)) = x1p;
            const ulonglong2* rp = (const ulonglong2*)(wrd + c * 32);
#pragma unroll
            for (int q = 0; q < 8; q++) {
                ulonglong2 w = rp[q];
                r[2 * q]     = fma2(w.x, x1p, r[2 * q]);
                r[2 * q + 1] = fma2(w.y, x1p, r[2 * q + 1]);
            }
        }
    }
    // ---- bn + relu on r ----
#pragma unroll
    for (int j = 0; j < 16; j++) {
        float a0, a1; unpack2(r[j], a0, a1);
        a0 = fmaxf(fmaf(srv[j], a0, trv[j]), 0.f);
        a1 = fmaxf(fmaf(srv[j], a1, trv[j]), 0.f);
        r[j] = pack2(a0, a1);
    }

    // ---- mapping skip (bn folded) ----
    float* sko = g_skip + ((size_t)b << 20) + pix;
#pragma unroll
    for (int ob = 0; ob < 4; ob++) {
        u64 acc[16];
        const ulonglong2* tp = (const ulonglong2*)(tmd + ob * 32);
#pragma unroll
        for (int q = 0; q < 8; q++) { ulonglong2 t = tp[q]; acc[2 * q] = t.x; acc[2 * q + 1] = t.y; }
#pragma unroll
        for (int ci = 0; ci < 32; ci++) {
            const ulonglong2* wp = (const ulonglong2*)(wmd + ci * 128 + ob * 32);
            u64 xc = xv[ci];
#pragma unroll
            for (int q = 0; q < 8; q++) {
                ulonglong2 w = wp[q];
                acc[2 * q]     = fma2(w.x, xc, acc[2 * q]);
                acc[2 * q + 1] = fma2(w.y, xc, acc[2 * q + 1]);
            }
        }
#pragma unroll
        for (int lc = 0; lc < 16; lc++)
            *(u64*)(sko + ((size_t)(ob * 16 + lc) << 14)) = acc[lc];
    }

    // ---- span: 196 outs in 14 chunks of 14 ----
    float* wvo = g_w + (((size_t)b * 196) << 14) + pix;
#pragma unroll
    for (int ch = 0; ch < 14; ch++) {
        int k0 = ch * 14;
        u64 wa[14];
#pragma unroll
        for (int k = 0; k < 14; k++) wa[k] = *(const u64*)(bsd + (k0 + k) * 2);
#pragma unroll
        for (int j = 0; j < 16; j++) {
            const ulonglong2* wp = (const ulonglong2*)(wsd + j * 392 + k0 * 2);
            u64 rj = r[j];
#pragma unroll
            for (int q = 0; q < 7; q++) {
                ulonglong2 w = wp[q];
                wa[2 * q]     = fma2(w.x, rj, wa[2 * q]);
                wa[2 * q + 1] = fma2(w.y, rj, wa[2 * q + 1]);
            }
        }
#pragma unroll
        for (int k = 0; k < 14; k++)
            *(u64*)(wvo + ((size_t)(k0 + k) << 14)) = wa[k];
    }
}

// ===========================================================================
// Kernel 2: involution + BN1 + GELU + conv2(BN2 folded) + skip + GELU
// Tile 16x8. 512 threads: thread = (pixel p 0..127, group g 0..3).
// f32x2 lanes here are CHANNEL pairs -> conv2 weights must be stored
// NON-duplicated [c][o] so a u64 load gives (w_o, w_{o+1}).  (R7 bug fix.)
// ===========================================================================
#define TW 16
#define TH 8
#define HW 22
#define HP 308           // 22*14 halo pixels
#define CSTR 68          // channel stride (17x16B => conflict-free LDS.128)
#define KM_X1S 0
#define KM_W2T (HP * CSTR)            // 20944, size 4096  [c][o] * bn2 scale
#define KM_S1V (KM_W2T + 4096)        // 25040
#define KM_T1V (KM_S1V + 64)
#define KM_T2V (KM_T1V + 64)
#define KM_FLOATS (KM_T2V + 64)       // 25232
#define KM_BYTES (KM_FLOATS * 4)      // 100928

__global__ void __launch_bounds__(512) k_main(
    const float* __restrict__ g1, const float* __restrict__ b1,
    const float* __restrict__ m1, const float* __restrict__ v1,
    const float* __restrict__ w2, const float* __restrict__ g2,
    const float* __restrict__ b2, const float* __restrict__ m2,
    const float* __restrict__ v2, float* __restrict__ out)
{
    float* x1s = smem + KM_X1S;
    float* w2t = smem + KM_W2T;
    float* s1v = smem + KM_S1V;
    float* t1v = smem + KM_T1V;
    float* t2v = smem + KM_T2V;

    const int tid = threadIdx.x;
    const int b = blockIdx.z;
    const int tx0 = blockIdx.x * TW, ty0 = blockIdx.y * TH;

    for (int i = tid; i < 4096; i += 512) {
        int c = i >> 6, o = i & 63;
        float s2 = g2[o] * rsqrtf(v2[o] + EPS);
        w2t[c * 64 + o] = w2[o * 64 + c] * s2;      // [c][o], NOT duplicated
    }
    if (tid < 64) {
        float s1 = g1[tid] * rsqrtf(v1[tid] + EPS);
        s1v[tid] = s1; t1v[tid] = b1[tid] - m1[tid] * s1;
        float s2 = g2[tid] * rsqrtf(v2[tid] + EPS);
        t2v[tid] = b2[tid] - m2[tid] * s2;
    }

    // halo load (zero padded): layout [halo_pixel][channel], stride CSTR
    const float* x1b = g_x1 + ((size_t)b << 20);
    for (int i = tid; i < HP * 64; i += 512) {
        int c = i / HP, hp = i - c * HP;
        int hy = hp / HW, hx = hp - hy * HW;
        int gy = ty0 - 3 + hy, gx = tx0 - 3 + hx;
        float v = 0.f;
        if (gy >= 0 && gy < 128 && gx >= 0 && gx < 128)
            v = __ldg(x1b + ((size_t)c << 14) + (gy << 7) + gx);
        x1s[hp * CSTR + c] = v;
    }
    __syncthreads();

    const int p = tid & 127, g = tid >> 7;
    const int py = p >> 4, px = p & 15;
    const int gy = ty0 + py, gx = tx0 + px;
    const int pix = (gy << 7) + gx;
    const int ch0 = g * 16;

    // ---- involution: 16 channels (8 f32x2 pairs), 49 taps ----
    float wq[49];
    const float* wvb = g_w + (((size_t)(b * 196 + g * 49)) << 14) + pix;
#pragma unroll
    for (int k = 0; k < 49; k++) wq[k] = __ldg(wvb + ((size_t)k << 14));

    u64 acc[8];
#pragma unroll
    for (int q = 0; q < 8; q++) acc[q] = 0ull;
#pragma unroll
    for (int di = 0; di < 7; di++) {
#pragma unroll
        for (int dj = 0; dj < 7; dj++) {
            float kw = wq[di * 7 + dj];
            u64 kp = pack2(kw, kw);                  // same tap for all channels: dup OK
            const ulonglong2* xp =
                (const ulonglong2*)(x1s + ((py + di) * HW + (px + dj)) * CSTR + ch0);
#pragma unroll
            for (int q = 0; q < 4; q++) {
                ulonglong2 xv = xp[q];
                acc[2 * q]     = fma2(kp, xv.x, acc[2 * q]);
                acc[2 * q + 1] = fma2(kp, xv.y, acc[2 * q + 1]);
            }
        }
    }
    // BN1 + GELU  (s/t pairs are per-channel: non-duplicated loads, correct)
    float y[16];
#pragma unroll
    for (int q = 0; q < 8; q++) {
        u64 s = *(const u64*)(s1v + ch0 + 2 * q);
        u64 t = *(const u64*)(t1v + ch0 + 2 * q);
        u64 v = fma2(acc[q], s, t);
        float a0, a1; unpack2(v, a0, a1);
        y[2 * q] = gelu1(a0); y[2 * q + 1] = gelu1(a1);
    }

    // ---- exchange y through smem (reuse halo region rows 0..127) ----
    __syncthreads();
#pragma unroll
    for (int c = 0; c < 16; c++) x1s[p * CSTR + ch0 + c] = y[c];
    __syncthreads();

    // ---- conv2 (bn2 folded): thread computes outs [ch0, ch0+16) ----
    u64 acc2[8];
#pragma unroll
    for (int q = 0; q < 8; q++) acc2[q] = *(const u64*)(t2v + ch0 + 2 * q);
    const float4* yb = (const float4*)(x1s + p * CSTR);
#pragma unroll
    for (int c4 = 0; c4 < 16; c4++) {
        float4 yv = yb[c4];
        float ya[4] = { yv.x, yv.y, yv.z, yv.w };
#pragma unroll
        for (int cc = 0; cc < 4; cc++) {
            int c = c4 * 4 + cc;
            u64 yp2 = pack2(ya[cc], ya[cc]);         // input scalar: dup OK
            const ulonglong2* wp = (const ulonglong2*)(w2t + c * 64 + ch0);
#pragma unroll
            for (int q = 0; q < 4; q++) {
                ulonglong2 w = wp[q];                // w.x=(o,o+1), w.y=(o+2,o+3)
                acc2[2 * q]     = fma2(w.x, yp2, acc2[2 * q]);
                acc2[2 * q + 1] = fma2(w.y, yp2, acc2[2 * q + 1]);
            }
        }
    }
    // ---- + skip, GELU, store ----
    const float* skb = g_skip + ((size_t)b << 20) + pix;
    float* ob = out + ((size_t)b << 20) + pix;
#pragma unroll
    for (int q = 0; q < 8; q++) {
        float a0, a1; unpack2(acc2[q], a0, a1);
        int o0 = ch0 + 2 * q;
        a0 += __ldg(skb + ((size_t)o0 << 14));
        a1 += __ldg(skb + ((size_t)(o0 + 1) << 14));
        ob[(size_t)o0 << 14]       = gelu1(a0);
        ob[(size_t)(o0 + 1) << 14] = gelu1(a1);
    }
}

// ===========================================================================
// Launch. Input order: x w1 wr gr br mr vr ws bs g1 b1 m1 v1
//                      w2 g2 b2 m2 v2 wm bmap gm betam mm vm
// ===========================================================================
extern "C" void kernel_launch(void* const* d_in, const int* in_sizes, int n_in,
                              void* d_out, int out_size)
{
    (void)in_sizes; (void)n_in; (void)out_size;
    const float* x     = (const float*)d_in[0];
    const float* w1    = (const float*)d_in[1];
    const float* wr    = (const float*)d_in[2];
    const float* gr    = (const float*)d_in[3];
    const float* br    = (const float*)d_in[4];
    const float* mr    = (const float*)d_in[5];
    const float* vr    = (const float*)d_in[6];
    const float* ws    = (const float*)d_in[7];
    const float* bs    = (const float*)d_in[8];
    const float* g1    = (const float*)d_in[9];
    const float* b1    = (const float*)d_in[10];
    const float* m1    = (const float*)d_in[11];
    const float* v1    = (const float*)d_in[12];
    const float* w2    = (const float*)d_in[13];
    const float* g2    = (const float*)d_in[14];
    const float* b2    = (const float*)d_in[15];
    const float* m2    = (const float*)d_in[16];
    const float* v2    = (const float*)d_in[17];
    const float* wm    = (const float*)d_in[18];
    const float* bmap  = (const float*)d_in[19];
    const float* gm    = (const float*)d_in[20];
    const float* betam = (const float*)d_in[21];
    const float* mm    = (const float*)d_in[22];
    const float* vm    = (const float*)d_in[23];
    float* out = (float*)d_out;

    cudaFuncSetAttribute(k_pre,  cudaFuncAttributeMaxDynamicSharedMemorySize, KP_BYTES);
    cudaFuncSetAttribute(k_main, cudaFuncAttributeMaxDynamicSharedMemorySize, KM_BYTES);

    k_pre<<<256, 128, KP_BYTES>>>(x, w1, wr, gr, br, mr, vr, ws, bs,
                                  wm, bmap, gm, betam, mm, vm);
    k_main<<<dim3(128 / TW, 128 / TH, 4), 512, KM_BYTES>>>(
        g1, b1, m1, v1, w2, g2, b2, m2, v2, out);
}

// round 9
// speedup vs baseline: 1.4371x; 1.2510x over previous
#include <cuda_runtime.h>
#include <math.h>

#define EPS 1e-5f
typedef unsigned long long u64;

// ---------------- scratch (allocation forbidden -> __device__ globals) ----
__device__ float g_x1[4u * 64u * 128u * 128u];     // gelu(conv1(x))
__device__ float g_skip[4u * 64u * 128u * 128u];   // bn(mapping(x))
__device__ float g_w[4u * 196u * 128u * 128u];     // involution weights

// ---------------- f32x2 helpers ----------------
__device__ __forceinline__ u64 pack2(float a, float b) {
    u64 r; asm("mov.b64 %0,{%1,%2};" : "=l"(r) : "f"(a), "f"(b)); return r;
}
__device__ __forceinline__ void unpack2(u64 v, float &a, float &b) {
    asm("mov.b64 {%0,%1},%2;" : "=f"(a), "=f"(b) : "l"(v));
}
__device__ __forceinline__ u64 fma2(u64 a, u64 b, u64 c) {
    u64 d; asm("fma.rn.f32x2 %0,%1,%2,%3;" : "=l"(d) : "l"(a), "l"(b), "l"(c)); return d;
}
__device__ __forceinline__ float gelu1(float v) {
    return 0.5f * v * (1.0f + erff(v * 0.70710678118654752440f));
}

// ===========================================================================
// Kernel 1: per pixel-PAIR (2 adjacent pixels in one f32x2 lane)
//   x1 = gelu(w1@x); r = relu(bn(wr@x1)); g_w = ws@r+bs; g_skip = bn(wm@x+b)
// f32x2 lanes = PIXEL pairs -> weights duplicated ([w,w]).
// R9: register-pressure rework — x values reloaded per output block (L1 hits)
// instead of a resident xv[32] (64 regs); ci loops rolled. No spills.
// ===========================================================================
#define KP_W1D 0        // 4096   [ci][o dup]
#define KP_WMD 4096     // 4096   [ci][o dup] (bn folded)
#define KP_WRD 8192     // 2048   [c][j dup]
#define KP_WSD 10240    // 6272   [j][k dup]
#define KP_TMD 16512    // 128    [o dup]  skip bias
#define KP_BSD 16640    // 392    [k dup]  span bias
#define KP_SRV 17032    // 16
#define KP_TRV 17048    // 16
#define KP_FLOATS 17064
#define KP_BYTES (KP_FLOATS * 4)

extern __shared__ __align__(16) float smem[];

__global__ void __launch_bounds__(128, 3) k_pre(
    const float* __restrict__ x,  const float* __restrict__ w1,
    const float* __restrict__ wr, const float* __restrict__ gr,
    const float* __restrict__ br, const float* __restrict__ mr,
    const float* __restrict__ vr, const float* __restrict__ ws,
    const float* __restrict__ bs, const float* __restrict__ wm,
    const float* __restrict__ bmap, const float* __restrict__ gm,
    const float* __restrict__ betam, const float* __restrict__ mm,
    const float* __restrict__ vm)
{
    float* w1d = smem + KP_W1D;
    float* wmd = smem + KP_WMD;
    float* wrd = smem + KP_WRD;
    float* wsd = smem + KP_WSD;
    float* tmd = smem + KP_TMD;
    float* bsd = smem + KP_BSD;
    float* srv = smem + KP_SRV;
    float* trv = smem + KP_TRV;

    const int tid = threadIdx.x;
    for (int i = tid; i < 2048; i += 128) {
        int ci = i >> 6, o = i & 63;
        float v = w1[o * 32 + ci];
        w1d[ci * 128 + 2 * o] = v; w1d[ci * 128 + 2 * o + 1] = v;
        float s = gm[o] * rsqrtf(vm[o] + EPS);
        float v2 = wm[o * 32 + ci] * s;
        wmd[ci * 128 + 2 * o] = v2; wmd[ci * 128 + 2 * o + 1] = v2;
    }
    for (int i = tid; i < 1024; i += 128) {
        int c = i >> 4, j = i & 15;
        float v = wr[j * 64 + c];
        wrd[c * 32 + 2 * j] = v; wrd[c * 32 + 2 * j + 1] = v;
    }
    for (int i = tid; i < 3136; i += 128) {
        int j = i / 196, k = i - j * 196;
        float v = ws[k * 16 + j];
        wsd[j * 392 + 2 * k] = v; wsd[j * 392 + 2 * k + 1] = v;
    }
    if (tid < 64) {
        float s = gm[tid] * rsqrtf(vm[tid] + EPS);
        float t = s * bmap[tid] + betam[tid] - mm[tid] * s;
        tmd[2 * tid] = t; tmd[2 * tid + 1] = t;
    }
    if (tid < 16) {
        float s = gr[tid] * rsqrtf(vr[tid] + EPS);
        srv[tid] = s; trv[tid] = br[tid] - mr[tid] * s;
    }
    for (int i = tid; i < 196; i += 128) {
        float v = bs[i]; bsd[2 * i] = v; bsd[2 * i + 1] = v;
    }
    __syncthreads();

    const int pp = blockIdx.x * 128 + tid;          // pair id, 32768 total
    const int p0 = pp << 1;
    const int b = p0 >> 14, pix = p0 & 16383;
    const float* xb = x + ((size_t)b << 19) + pix;

    // ---- conv1 + gelu (+ fused reduce accumulation) ----
    u64 r[16];
#pragma unroll
    for (int j = 0; j < 16; j++) r[j] = 0ull;
    float* x1o = g_x1 + ((size_t)b << 20) + pix;
#pragma unroll
    for (int ob = 0; ob < 4; ob++) {
        u64 acc[16];
#pragma unroll
        for (int q = 0; q < 16; q++) acc[q] = 0ull;
#pragma unroll 4
        for (int ci = 0; ci < 32; ci++) {
            u64 xc = *(const u64*)(xb + ((size_t)ci << 14));   // L1 hit after ob=0
            const ulonglong2* wp = (const ulonglong2*)(w1d + ci * 128 + ob * 32);
#pragma unroll
            for (int q = 0; q < 8; q++) {
                ulonglong2 w = wp[q];
                acc[2 * q]     = fma2(w.x, xc, acc[2 * q]);
                acc[2 * q + 1] = fma2(w.y, xc, acc[2 * q + 1]);
            }
        }
#pragma unroll
        for (int lc = 0; lc < 16; lc++) {
            int c = ob * 16 + lc;
            float a0, a1; unpack2(acc[lc], a0, a1);
            u64 x1p = pack2(gelu1(a0), gelu1(a1));
            *(u64*)(x1o + ((size_t)c << 14)) = x1p;
            const ulonglong2* rp = (const ulonglong2*)(wrd + c * 32);
#pragma unroll
            for (int q = 0; q < 8; q++) {
                ulonglong2 w = rp[q];
                r[2 * q]     = fma2(w.x, x1p, r[2 * q]);
                r[2 * q + 1] = fma2(w.y, x1p, r[2 * q + 1]);
            }
        }
    }
    // ---- bn + relu on r ----
#pragma unroll
    for (int j = 0; j < 16; j++) {
        float a0, a1; unpack2(r[j], a0, a1);
        a0 = fmaxf(fmaf(srv[j], a0, trv[j]), 0.f);
        a1 = fmaxf(fmaf(srv[j], a1, trv[j]), 0.f);
        r[j] = pack2(a0, a1);
    }

    // ---- mapping skip (bn folded), x reloaded from L1/L2 ----
    float* sko = g_skip + ((size_t)b << 20) + pix;
#pragma unroll
    for (int ob = 0; ob < 4; ob++) {
        u64 acc[16];
        const ulonglong2* tp = (const ulonglong2*)(tmd + ob * 32);
#pragma unroll
        for (int q = 0; q < 8; q++) { ulonglong2 t = tp[q]; acc[2 * q] = t.x; acc[2 * q + 1] = t.y; }
#pragma unroll 4
        for (int ci = 0; ci < 32; ci++) {
            u64 xc = *(const u64*)(xb + ((size_t)ci << 14));
            const ulonglong2* wp = (const ulonglong2*)(wmd + ci * 128 + ob * 32);
#pragma unroll
            for (int q = 0; q < 8; q++) {
                ulonglong2 w = wp[q];
                acc[2 * q]     = fma2(w.x, xc, acc[2 * q]);
                acc[2 * q + 1] = fma2(w.y, xc, acc[2 * q + 1]);
            }
        }
#pragma unroll
        for (int lc = 0; lc < 16; lc++)
            *(u64*)(sko + ((size_t)(ob * 16 + lc) << 14)) = acc[lc];
    }

    // ---- span: 196 outs in 14 chunks of 14 ----
    float* wvo = g_w + (((size_t)b * 196) << 14) + pix;
#pragma unroll
    for (int ch = 0; ch < 14; ch++) {
        int k0 = ch * 14;
        u64 wa[14];
#pragma unroll
        for (int k = 0; k < 14; k++) wa[k] = *(const u64*)(bsd + (k0 + k) * 2);
#pragma unroll 4
        for (int j = 0; j < 16; j++) {
            const ulonglong2* wp = (const ulonglong2*)(wsd + j * 392 + k0 * 2);
            u64 rj = r[j];
#pragma unroll
            for (int q = 0; q < 7; q++) {
                ulonglong2 w = wp[q];
                wa[2 * q]     = fma2(w.x, rj, wa[2 * q]);
                wa[2 * q + 1] = fma2(w.y, rj, wa[2 * q + 1]);
            }
        }
#pragma unroll
        for (int k = 0; k < 14; k++)
            *(u64*)(wvo + ((size_t)(k0 + k) << 14)) = wa[k];
    }
}

// ===========================================================================
// Kernel 2: involution + BN1 + GELU + conv2(BN2 folded) + skip + GELU
// Tile 16x8. 512 threads: thread = (pixel p 0..127, group g 0..3).
// R9: wq[49] register array removed (weights loaded 7-at-a-time inside the
// di loop) + __launch_bounds__(512,2) -> 2 CTAs/SM, 32 warps.
// ===========================================================================
#define TW 16
#define TH 8
#define HW 22
#define HP 308           // 22*14 halo pixels
#define CSTR 68          // channel stride (17x16B => conflict-free LDS.128)
#define KM_X1S 0
#define KM_W2T (HP * CSTR)            // 20944, size 4096  [c][o] * bn2 scale
#define KM_S1V (KM_W2T + 4096)        // 25040
#define KM_T1V (KM_S1V + 64)
#define KM_T2V (KM_T1V + 64)
#define KM_FLOATS (KM_T2V + 64)       // 25232
#define KM_BYTES (KM_FLOATS * 4)      // 100928 (x2 CTAs = 197KB < 228KB)

__global__ void __launch_bounds__(512, 2) k_main(
    const float* __restrict__ g1, const float* __restrict__ b1,
    const float* __restrict__ m1, const float* __restrict__ v1,
    const float* __restrict__ w2, const float* __restrict__ g2,
    const float* __restrict__ b2, const float* __restrict__ m2,
    const float* __restrict__ v2, float* __restrict__ out)
{
    float* x1s = smem + KM_X1S;
    float* w2t = smem + KM_W2T;
    float* s1v = smem + KM_S1V;
    float* t1v = smem + KM_T1V;
    float* t2v = smem + KM_T2V;

    const int tid = threadIdx.x;
    const int b = blockIdx.z;
    const int tx0 = blockIdx.x * TW, ty0 = blockIdx.y * TH;

    for (int i = tid; i < 4096; i += 512) {
        int c = i >> 6, o = i & 63;
        float s2 = g2[o] * rsqrtf(v2[o] + EPS);
        w2t[c * 64 + o] = w2[o * 64 + c] * s2;      // [c][o], NOT duplicated
    }
    if (tid < 64) {
        float s1 = g1[tid] * rsqrtf(v1[tid] + EPS);
        s1v[tid] = s1; t1v[tid] = b1[tid] - m1[tid] * s1;
        float s2 = g2[tid] * rsqrtf(v2[tid] + EPS);
        t2v[tid] = b2[tid] - m2[tid] * s2;
    }

    // halo load (zero padded): layout [halo_pixel][channel], stride CSTR
    const float* x1b = g_x1 + ((size_t)b << 20);
    for (int i = tid; i < HP * 64; i += 512) {
        int c = i / HP, hp = i - c * HP;
        int hy = hp / HW, hx = hp - hy * HW;
        int gy = ty0 - 3 + hy, gx = tx0 - 3 + hx;
        float v = 0.f;
        if (gy >= 0 && gy < 128 && gx >= 0 && gx < 128)
            v = __ldg(x1b + ((size_t)c << 14) + (gy << 7) + gx);
        x1s[hp * CSTR + c] = v;
    }
    __syncthreads();

    const int p = tid & 127, g = tid >> 7;
    const int py = p >> 4, px = p & 15;
    const int gy = ty0 + py, gx = tx0 + px;
    const int pix = (gy << 7) + gx;
    const int ch0 = g * 16;

    // ---- involution: 16 channels (8 f32x2 pairs), 49 taps ----
    const float* wvb = g_w + (((size_t)(b * 196 + g * 49)) << 14) + pix;

    u64 acc[8];
#pragma unroll
    for (int q = 0; q < 8; q++) acc[q] = 0ull;
#pragma unroll
    for (int di = 0; di < 7; di++) {
        float w7[7];
#pragma unroll
        for (int dj = 0; dj < 7; dj++)
            w7[dj] = __ldg(wvb + ((size_t)(di * 7 + dj) << 14));
        const float* rowb = x1s + ((py + di) * HW + px) * CSTR + ch0;
#pragma unroll
        for (int dj = 0; dj < 7; dj++) {
            u64 kp = pack2(w7[dj], w7[dj]);
            const ulonglong2* xp = (const ulonglong2*)(rowb + dj * CSTR);
#pragma unroll
            for (int q = 0; q < 4; q++) {
                ulonglong2 xv = xp[q];
                acc[2 * q]     = fma2(kp, xv.x, acc[2 * q]);
                acc[2 * q + 1] = fma2(kp, xv.y, acc[2 * q + 1]);
            }
        }
    }
    // BN1 + GELU
    float y[16];
#pragma unroll
    for (int q = 0; q < 8; q++) {
        u64 s = *(const u64*)(s1v + ch0 + 2 * q);
        u64 t = *(const u64*)(t1v + ch0 + 2 * q);
        u64 v = fma2(acc[q], s, t);
        float a0, a1; unpack2(v, a0, a1);
        y[2 * q] = gelu1(a0); y[2 * q + 1] = gelu1(a1);
    }

    // ---- exchange y through smem (reuse halo region rows 0..127) ----
    __syncthreads();
#pragma unroll
    for (int c = 0; c < 16; c++) x1s[p * CSTR + ch0 + c] = y[c];
    __syncthreads();

    // ---- conv2 (bn2 folded): thread computes outs [ch0, ch0+16) ----
    u64 acc2[8];
#pragma unroll
    for (int q = 0; q < 8; q++) acc2[q] = *(const u64*)(t2v + ch0 + 2 * q);
    const float4* yb = (const float4*)(x1s + p * CSTR);
#pragma unroll 4
    for (int c4 = 0; c4 < 16; c4++) {
        float4 yv = yb[c4];
        float ya[4] = { yv.x, yv.y, yv.z, yv.w };
#pragma unroll
        for (int cc = 0; cc < 4; cc++) {
            int c = c4 * 4 + cc;
            u64 yp2 = pack2(ya[cc], ya[cc]);
            const ulonglong2* wp = (const ulonglong2*)(w2t + c * 64 + ch0);
#pragma unroll
            for (int q = 0; q < 4; q++) {
                ulonglong2 w = wp[q];                // w.x=(o,o+1), w.y=(o+2,o+3)
                acc2[2 * q]     = fma2(w.x, yp2, acc2[2 * q]);
                acc2[2 * q + 1] = fma2(w.y, yp2, acc2[2 * q + 1]);
            }
        }
    }
    // ---- + skip, GELU, store ----
    const float* skb = g_skip + ((size_t)b << 20) + pix;
    float* ob = out + ((size_t)b << 20) + pix;
#pragma unroll
    for (int q = 0; q < 8; q++) {
        float a0, a1; unpack2(acc2[q], a0, a1);
        int o0 = ch0 + 2 * q;
        a0 += __ldg(skb + ((size_t)o0 << 14));
        a1 += __ldg(skb + ((size_t)(o0 + 1) << 14));
        ob[(size_t)o0 << 14]       = gelu1(a0);
        ob[(size_t)(o0 + 1) << 14] = gelu1(a1);
    }
}

// ===========================================================================
// Launch. Input order: x w1 wr gr br mr vr ws bs g1 b1 m1 v1
//                      w2 g2 b2 m2 v2 wm bmap gm betam mm vm
// ===========================================================================
extern "C" void kernel_launch(void* const* d_in, const int* in_sizes, int n_in,
                              void* d_out, int out_size)
{
    (void)in_sizes; (void)n_in; (void)out_size;
    const float* x     = (const float*)d_in[0];
    const float* w1    = (const float*)d_in[1];
    const float* wr    = (const float*)d_in[2];
    const float* gr    = (const float*)d_in[3];
    const float* br    = (const float*)d_in[4];
    const float* mr    = (const float*)d_in[5];
    const float* vr    = (const float*)d_in[6];
    const float* ws    = (const float*)d_in[7];
    const float* bs    = (const float*)d_in[8];
    const float* g1    = (const float*)d_in[9];
    const float* b1    = (const float*)d_in[10];
    const float* m1    = (const float*)d_in[11];
    const float* v1    = (const float*)d_in[12];
    const float* w2    = (const float*)d_in[13];
    const float* g2    = (const float*)d_in[14];
    const float* b2    = (const float*)d_in[15];
    const float* m2    = (const float*)d_in[16];
    const float* v2    = (const float*)d_in[17];
    const float* wm    = (const float*)d_in[18];
    const float* bmap  = (const float*)d_in[19];
    const float* gm    = (const float*)d_in[20];
    const float* betam = (const float*)d_in[21];
    const float* mm    = (const float*)d_in[22];
    const float* vm    = (const float*)d_in[23];
    float* out = (float*)d_out;

    cudaFuncSetAttribute(k_pre,  cudaFuncAttributeMaxDynamicSharedMemorySize, KP_BYTES);
    cudaFuncSetAttribute(k_main, cudaFuncAttributeMaxDynamicSharedMemorySize, KM_BYTES);

    k_pre<<<256, 128, KP_BYTES>>>(x, w1, wr, gr, br, mr, vr, ws, bs,
                                  wm, bmap, gm, betam, mm, vm);
    k_main<<<dim3(128 / TW, 128 / TH, 4), 512, KM_BYTES>>>(
        g1, b1, m1, v1, w2, g2, b2, m2, v2, out);
}

// round 10
// speedup vs baseline: 1.5798x; 1.0993x over previous
#include <cuda_runtime.h>
#include <math.h>

#define EPS 1e-5f
typedef unsigned long long u64;

// ---------------- scratch (allocation forbidden -> __device__ globals) ----
__device__ float g_x1[4u * 64u * 128u * 128u];     // gelu(conv1(x))
__device__ float g_skip[4u * 64u * 128u * 128u];   // bn(mapping(x))
__device__ float g_w[4u * 196u * 128u * 128u];     // involution weights

// ---------------- f32x2 helpers ----------------
__device__ __forceinline__ u64 pack2(float a, float b) {
    u64 r; asm("mov.b64 %0,{%1,%2};" : "=l"(r) : "f"(a), "f"(b)); return r;
}
__device__ __forceinline__ void unpack2(u64 v, float &a, float &b) {
    asm("mov.b64 {%0,%1},%2;" : "=f"(a), "=f"(b) : "l"(v));
}
__device__ __forceinline__ u64 fma2(u64 a, u64 b, u64 c) {
    u64 d; asm("fma.rn.f32x2 %0,%1,%2,%3;" : "=l"(d) : "l"(a), "l"(b), "l"(c)); return d;
}
__device__ __forceinline__ float gelu1(float v) {
    return 0.5f * v * (1.0f + erff(v * 0.70710678118654752440f));
}

// ===========================================================================
// Kernel 1 (R10 rewrite): ONE PIXEL per thread, f32x2 lanes = CHANNEL pairs.
//   x1 = gelu(w1@x); r = relu(bn(wr@x1)); g_w = ws@r+bs; g_skip = bn(wm@x+b)
// 65536 threads (512 CTAs x 128) -> 3 CTAs/SM resident, 12 warps/SM.
// Weights NON-duplicated: one broadcast LDS.128 = 2 fma2 operand pairs.
// ===========================================================================
#define KP_W1N 0        // 2048  [ci][o]
#define KP_WMN 2048     // 2048  [ci][o] (bn folded)
#define KP_WRN 4096     // 1024  [c][j]
#define KP_WSN 5120     // 3136  [j][k]
#define KP_TM  8256     // 64    skip bias (bn folded)
#define KP_BSN 8320     // 196   span bias
#define KP_SRV 8516     // 16
#define KP_TRV 8532     // 16
#define KP_FLOATS 8548
#define KP_BYTES (KP_FLOATS * 4)

extern __shared__ __align__(16) float smem[];

__global__ void __launch_bounds__(128, 3) k_pre(
    const float* __restrict__ x,  const float* __restrict__ w1,
    const float* __restrict__ wr, const float* __restrict__ gr,
    const float* __restrict__ br, const float* __restrict__ mr,
    const float* __restrict__ vr, const float* __restrict__ ws,
    const float* __restrict__ bs, const float* __restrict__ wm,
    const float* __restrict__ bmap, const float* __restrict__ gm,
    const float* __restrict__ betam, const float* __restrict__ mm,
    const float* __restrict__ vm)
{
    float* w1n = smem + KP_W1N;
    float* wmn = smem + KP_WMN;
    float* wrn = smem + KP_WRN;
    float* wsn = smem + KP_WSN;
    float* tmv = smem + KP_TM;
    float* bsn = smem + KP_BSN;
    float* srv = smem + KP_SRV;
    float* trv = smem + KP_TRV;

    const int tid = threadIdx.x;
    for (int i = tid; i < 2048; i += 128) {
        int ci = i >> 6, o = i & 63;
        w1n[ci * 64 + o] = w1[o * 32 + ci];
        float s = gm[o] * rsqrtf(vm[o] + EPS);
        wmn[ci * 64 + o] = wm[o * 32 + ci] * s;
    }
    for (int i = tid; i < 1024; i += 128) {
        int c = i >> 4, j = i & 15;
        wrn[c * 16 + j] = wr[j * 64 + c];
    }
    for (int i = tid; i < 3136; i += 128) {
        int j = i / 196, k = i - j * 196;
        wsn[j * 196 + k] = ws[k * 16 + j];
    }
    if (tid < 64) {
        float s = gm[tid] * rsqrtf(vm[tid] + EPS);
        tmv[tid] = s * bmap[tid] + betam[tid] - mm[tid] * s;
    }
    if (tid < 16) {
        float s = gr[tid] * rsqrtf(vr[tid] + EPS);
        srv[tid] = s; trv[tid] = br[tid] - mr[tid] * s;
    }
    for (int i = tid; i < 196; i += 128) bsn[i] = bs[i];
    __syncthreads();

    const int pg = blockIdx.x * 128 + tid;          // global pixel id
    const int b = pg >> 14, pix = pg & 16383;
    const float* xb = x + ((size_t)b << 19) + pix;

    float xv[32];
#pragma unroll
    for (int ci = 0; ci < 32; ci++) xv[ci] = __ldg(xb + ((size_t)ci << 14));

    // ---- conv1 + gelu, fused reduce accumulation ----
    u64 r[8];
#pragma unroll
    for (int q = 0; q < 8; q++) r[q] = 0ull;
    float* x1o = g_x1 + ((size_t)b << 20) + pix;
#pragma unroll
    for (int ob = 0; ob < 2; ob++) {                 // 2 blocks of 32 output ch
        u64 acc[16];
#pragma unroll
        for (int q = 0; q < 16; q++) acc[q] = 0ull;
#pragma unroll 4
        for (int ci = 0; ci < 32; ci++) {
            u64 xd = pack2(xv[ci], xv[ci]);
            const ulonglong2* wp = (const ulonglong2*)(w1n + ci * 64 + ob * 32);
#pragma unroll
            for (int q = 0; q < 8; q++) {
                ulonglong2 w = wp[q];                // (o,o+1),(o+2,o+3)
                acc[2 * q]     = fma2(w.x, xd, acc[2 * q]);
                acc[2 * q + 1] = fma2(w.y, xd, acc[2 * q + 1]);
            }
        }
#pragma unroll
        for (int lc = 0; lc < 16; lc++) {
            int c0 = ob * 32 + 2 * lc;
            float v0, v1; unpack2(acc[lc], v0, v1);
            float g0 = gelu1(v0), g1 = gelu1(v1);
            x1o[(size_t)c0 << 14]       = g0;
            x1o[(size_t)(c0 + 1) << 14] = g1;
            u64 g0d = pack2(g0, g0), g1d = pack2(g1, g1);
            const ulonglong2* r0 = (const ulonglong2*)(wrn + c0 * 16);
            const ulonglong2* r1 = (const ulonglong2*)(wrn + (c0 + 1) * 16);
#pragma unroll
            for (int q = 0; q < 4; q++) {
                ulonglong2 wA = r0[q];
                r[2 * q]     = fma2(wA.x, g0d, r[2 * q]);
                r[2 * q + 1] = fma2(wA.y, g0d, r[2 * q + 1]);
                ulonglong2 wB = r1[q];
                r[2 * q]     = fma2(wB.x, g1d, r[2 * q]);
                r[2 * q + 1] = fma2(wB.y, g1d, r[2 * q + 1]);
            }
        }
    }
    // ---- bn + relu on r -> scalars ----
    float r16[16];
#pragma unroll
    for (int q = 0; q < 8; q++) {
        float a0, a1; unpack2(r[q], a0, a1);
        r16[2 * q]     = fmaxf(fmaf(srv[2 * q],     a0, trv[2 * q]),     0.f);
        r16[2 * q + 1] = fmaxf(fmaf(srv[2 * q + 1], a1, trv[2 * q + 1]), 0.f);
    }

    // ---- mapping skip (bn folded) ----
    float* sko = g_skip + ((size_t)b << 20) + pix;
#pragma unroll
    for (int ob = 0; ob < 2; ob++) {
        u64 acc[16];
        const ulonglong2* tp = (const ulonglong2*)(tmv + ob * 32);
#pragma unroll
        for (int q = 0; q < 8; q++) { ulonglong2 t = tp[q]; acc[2 * q] = t.x; acc[2 * q + 1] = t.y; }
#pragma unroll 4
        for (int ci = 0; ci < 32; ci++) {
            u64 xd = pack2(xv[ci], xv[ci]);
            const ulonglong2* wp = (const ulonglong2*)(wmn + ci * 64 + ob * 32);
#pragma unroll
            for (int q = 0; q < 8; q++) {
                ulonglong2 w = wp[q];
                acc[2 * q]     = fma2(w.x, xd, acc[2 * q]);
                acc[2 * q + 1] = fma2(w.y, xd, acc[2 * q + 1]);
            }
        }
#pragma unroll
        for (int lc = 0; lc < 16; lc++) {
            int c0 = ob * 32 + 2 * lc;
            float s0, s1; unpack2(acc[lc], s0, s1);
            sko[(size_t)c0 << 14]       = s0;
            sko[(size_t)(c0 + 1) << 14] = s1;
        }
    }

    // ---- span: 196 outs in 7 chunks of 28 (14 u64 k-pairs) ----
    float* wvo = g_w + (((size_t)b * 196) << 14) + pix;
#pragma unroll
    for (int ch = 0; ch < 7; ch++) {
        int k0 = ch * 28;
        u64 wa[14];
        const u64* bp = (const u64*)(bsn + k0);
#pragma unroll
        for (int k = 0; k < 14; k++) wa[k] = bp[k];
#pragma unroll 4
        for (int j = 0; j < 16; j++) {
            u64 rd = pack2(r16[j], r16[j]);
            const ulonglong2* wp = (const ulonglong2*)(wsn + j * 196 + k0);
#pragma unroll
            for (int q = 0; q < 7; q++) {
                ulonglong2 w = wp[q];
                wa[2 * q]     = fma2(w.x, rd, wa[2 * q]);
                wa[2 * q + 1] = fma2(w.y, rd, wa[2 * q + 1]);
            }
        }
#pragma unroll
        for (int k = 0; k < 14; k++) {
            float w0, w1v; unpack2(wa[k], w0, w1v);
            wvo[(size_t)(k0 + 2 * k) << 14]     = w0;
            wvo[(size_t)(k0 + 2 * k + 1) << 14] = w1v;
        }
    }
}

// ===========================================================================
// Kernel 2 (unchanged from R9): involution + BN1 + GELU + conv2 + skip + GELU
// Tile 16x8. 512 threads: thread = (pixel p 0..127, group g 0..3). 2 CTAs/SM.
// ===========================================================================
#define TW 16
#define TH 8
#define HW 22
#define HP 308           // 22*14 halo pixels
#define CSTR 68          // channel stride (17x16B => conflict-free LDS.128)
#define KM_X1S 0
#define KM_W2T (HP * CSTR)            // 20944, size 4096  [c][o] * bn2 scale
#define KM_S1V (KM_W2T + 4096)        // 25040
#define KM_T1V (KM_S1V + 64)
#define KM_T2V (KM_T1V + 64)
#define KM_FLOATS (KM_T2V + 64)       // 25232
#define KM_BYTES (KM_FLOATS * 4)      // 100928 (x2 CTAs = 197KB < 228KB)

__global__ void __launch_bounds__(512, 2) k_main(
    const float* __restrict__ g1, const float* __restrict__ b1,
    const float* __restrict__ m1, const float* __restrict__ v1,
    const float* __restrict__ w2, const float* __restrict__ g2,
    const float* __restrict__ b2, const float* __restrict__ m2,
    const float* __restrict__ v2, float* __restrict__ out)
{
    float* x1s = smem + KM_X1S;
    float* w2t = smem + KM_W2T;
    float* s1v = smem + KM_S1V;
    float* t1v = smem + KM_T1V;
    float* t2v = smem + KM_T2V;

    const int tid = threadIdx.x;
    const int b = blockIdx.z;
    const int tx0 = blockIdx.x * TW, ty0 = blockIdx.y * TH;

    for (int i = tid; i < 4096; i += 512) {
        int c = i >> 6, o = i & 63;
        float s2 = g2[o] * rsqrtf(v2[o] + EPS);
        w2t[c * 64 + o] = w2[o * 64 + c] * s2;      // [c][o], NOT duplicated
    }
    if (tid < 64) {
        float s1 = g1[tid] * rsqrtf(v1[tid] + EPS);
        s1v[tid] = s1; t1v[tid] = b1[tid] - m1[tid] * s1;
        float s2 = g2[tid] * rsqrtf(v2[tid] + EPS);
        t2v[tid] = b2[tid] - m2[tid] * s2;
    }

    // halo load (zero padded): layout [halo_pixel][channel], stride CSTR
    const float* x1b = g_x1 + ((size_t)b << 20);
    for (int i = tid; i < HP * 64; i += 512) {
        int c = i / HP, hp = i - c * HP;
        int hy = hp / HW, hx = hp - hy * HW;
        int gy = ty0 - 3 + hy, gx = tx0 - 3 + hx;
        float v = 0.f;
        if (gy >= 0 && gy < 128 && gx >= 0 && gx < 128)
            v = __ldg(x1b + ((size_t)c << 14) + (gy << 7) + gx);
        x1s[hp * CSTR + c] = v;
    }
    __syncthreads();

    const int p = tid & 127, g = tid >> 7;
    const int py = p >> 4, px = p & 15;
    const int gy = ty0 + py, gx = tx0 + px;
    const int pix = (gy << 7) + gx;
    const int ch0 = g * 16;

    // ---- involution: 16 channels (8 f32x2 pairs), 49 taps ----
    const float* wvb = g_w + (((size_t)(b * 196 + g * 49)) << 14) + pix;

    u64 acc[8];
#pragma unroll
    for (int q = 0; q < 8; q++) acc[q] = 0ull;
#pragma unroll
    for (int di = 0; di < 7; di++) {
        float w7[7];
#pragma unroll
        for (int dj = 0; dj < 7; dj++)
            w7[dj] = __ldg(wvb + ((size_t)(di * 7 + dj) << 14));
        const float* rowb = x1s + ((py + di) * HW + px) * CSTR + ch0;
#pragma unroll
        for (int dj = 0; dj < 7; dj++) {
            u64 kp = pack2(w7[dj], w7[dj]);
            const ulonglong2* xp = (const ulonglong2*)(rowb + dj * CSTR);
#pragma unroll
            for (int q = 0; q < 4; q++) {
                ulonglong2 xv = xp[q];
                acc[2 * q]     = fma2(kp, xv.x, acc[2 * q]);
                acc[2 * q + 1] = fma2(kp, xv.y, acc[2 * q + 1]);
            }
        }
    }
    // BN1 + GELU
    float y[16];
#pragma unroll
    for (int q = 0; q < 8; q++) {
        u64 s = *(const u64*)(s1v + ch0 + 2 * q);
        u64 t = *(const u64*)(t1v + ch0 + 2 * q);
        u64 v = fma2(acc[q], s, t);
        float a0, a1; unpack2(v, a0, a1);
        y[2 * q] = gelu1(a0); y[2 * q + 1] = gelu1(a1);
    }

    // ---- exchange y through smem (reuse halo region rows 0..127) ----
    __syncthreads();
#pragma unroll
    for (int c = 0; c < 16; c++) x1s[p * CSTR + ch0 + c] = y[c];
    __syncthreads();

    // ---- conv2 (bn2 folded): thread computes outs [ch0, ch0+16) ----
    u64 acc2[8];
#pragma unroll
    for (int q = 0; q < 8; q++) acc2[q] = *(const u64*)(t2v + ch0 + 2 * q);
    const float4* yb = (const float4*)(x1s + p * CSTR);
#pragma unroll 4
    for (int c4 = 0; c4 < 16; c4++) {
        float4 yv = yb[c4];
        float ya[4] = { yv.x, yv.y, yv.z, yv.w };
#pragma unroll
        for (int cc = 0; cc < 4; cc++) {
            int c = c4 * 4 + cc;
            u64 yp2 = pack2(ya[cc], ya[cc]);
            const ulonglong2* wp = (const ulonglong2*)(w2t + c * 64 + ch0);
#pragma unroll
            for (int q = 0; q < 4; q++) {
                ulonglong2 w = wp[q];                // w.x=(o,o+1), w.y=(o+2,o+3)
                acc2[2 * q]     = fma2(w.x, yp2, acc2[2 * q]);
                acc2[2 * q + 1] = fma2(w.y, yp2, acc2[2 * q + 1]);
            }
        }
    }
    // ---- + skip, GELU, store ----
    const float* skb = g_skip + ((size_t)b << 20) + pix;
    float* ob = out + ((size_t)b << 20) + pix;
#pragma unroll
    for (int q = 0; q < 8; q++) {
        float a0, a1; unpack2(acc2[q], a0, a1);
        int o0 = ch0 + 2 * q;
        a0 += __ldg(skb + ((size_t)o0 << 14));
        a1 += __ldg(skb + ((size_t)(o0 + 1) << 14));
        ob[(size_t)o0 << 14]       = gelu1(a0);
        ob[(size_t)(o0 + 1) << 14] = gelu1(a1);
    }
}

// ===========================================================================
// Launch. Input order: x w1 wr gr br mr vr ws bs g1 b1 m1 v1
//                      w2 g2 b2 m2 v2 wm bmap gm betam mm vm
// ===========================================================================
extern "C" void kernel_launch(void* const* d_in, const int* in_sizes, int n_in,
                              void* d_out, int out_size)
{
    (void)in_sizes; (void)n_in; (void)out_size;
    const float* x     = (const float*)d_in[0];
    const float* w1    = (const float*)d_in[1];
    const float* wr    = (const float*)d_in[2];
    const float* gr    = (const float*)d_in[3];
    const float* br    = (const float*)d_in[4];
    const float* mr    = (const float*)d_in[5];
    const float* vr    = (const float*)d_in[6];
    const float* ws    = (const float*)d_in[7];
    const float* bs    = (const float*)d_in[8];
    const float* g1    = (const float*)d_in[9];
    const float* b1    = (const float*)d_in[10];
    const float* m1    = (const float*)d_in[11];
    const float* v1    = (const float*)d_in[12];
    const float* w2    = (const float*)d_in[13];
    const float* g2    = (const float*)d_in[14];
    const float* b2    = (const float*)d_in[15];
    const float* m2    = (const float*)d_in[16];
    const float* v2    = (const float*)d_in[17];
    const float* wm    = (const float*)d_in[18];
    const float* bmap  = (const float*)d_in[19];
    const float* gm    = (const float*)d_in[20];
    const float* betam = (const float*)d_in[21];
    const float* mm    = (const float*)d_in[22];
    const float* vm    = (const float*)d_in[23];
    float* out = (float*)d_out;

    cudaFuncSetAttribute(k_pre,  cudaFuncAttributeMaxDynamicSharedMemorySize, KP_BYTES);
    cudaFuncSetAttribute(k_main, cudaFuncAttributeMaxDynamicSharedMemorySize, KM_BYTES);

    k_pre<<<512, 128, KP_BYTES>>>(x, w1, wr, gr, br, mr, vr, ws, bs,
                                  wm, bmap, gm, betam, mm, vm);
    k_main<<<dim3(128 / TW, 128 / TH, 4), 512, KM_BYTES>>>(
        g1, b1, m1, v1, w2, g2, b2, m2, v2, out);
}

// round 11
// speedup vs baseline: 1.7229x; 1.0906x over previous
#include <cuda_runtime.h>
#include <math.h>

#define EPS 1e-5f
typedef unsigned long long u64;

// ---------------- scratch (allocation forbidden -> __device__ globals) ----
__device__ float g_x1[4u * 64u * 128u * 128u];     // gelu(conv1(x))   16.8 MB
__device__ float g_skip[4u * 64u * 128u * 128u];   // bn(mapping(x))   16.8 MB
__device__ float g_r[4u * 16u * 128u * 128u];      // relu(bn(reduce))  4.2 MB

// ---------------- f32x2 helpers ----------------
__device__ __forceinline__ u64 pack2(float a, float b) {
    u64 r; asm("mov.b64 %0,{%1,%2};" : "=l"(r) : "f"(a), "f"(b)); return r;
}
__device__ __forceinline__ void unpack2(u64 v, float &a, float &b) {
    asm("mov.b64 {%0,%1},%2;" : "=f"(a), "=f"(b) : "l"(v));
}
__device__ __forceinline__ u64 fma2(u64 a, u64 b, u64 c) {
    u64 d; asm("fma.rn.f32x2 %0,%1,%2,%3;" : "=l"(d) : "l"(a), "l"(b), "l"(c)); return d;
}
__device__ __forceinline__ float gelu1(float v) {
    return 0.5f * v * (1.0f + erff(v * 0.70710678118654752440f));
}

// ===========================================================================
// Kernel 1 (R11): ONE PIXEL per thread, f32x2 lanes = CHANNEL pairs.
//   x1 = gelu(w1@x);  r = relu(bn(wr@x1)) -> g_r;  skip = bn(wm@x+b)
// Span (ws@r+bs) moved into k_main: kills the 51 MB g_w round-trip.
// ===========================================================================
#define KP_W1N 0        // 2048  [ci][o]
#define KP_WMN 2048     // 2048  [ci][o] (bn folded)
#define KP_WRN 4096     // 1024  [c][j]
#define KP_TM  5120     // 64    skip bias (bn folded)
#define KP_SRV 5184     // 16
#define KP_TRV 5200     // 16
#define KP_FLOATS 5216
#define KP_BYTES (KP_FLOATS * 4)

extern __shared__ __align__(16) float smem[];

__global__ void __launch_bounds__(128, 3) k_pre(
    const float* __restrict__ x,  const float* __restrict__ w1,
    const float* __restrict__ wr, const float* __restrict__ gr,
    const float* __restrict__ br, const float* __restrict__ mr,
    const float* __restrict__ vr, const float* __restrict__ wm,
    const float* __restrict__ bmap, const float* __restrict__ gm,
    const float* __restrict__ betam, const float* __restrict__ mm,
    const float* __restrict__ vm)
{
    float* w1n = smem + KP_W1N;
    float* wmn = smem + KP_WMN;
    float* wrn = smem + KP_WRN;
    float* tmv = smem + KP_TM;
    float* srv = smem + KP_SRV;
    float* trv = smem + KP_TRV;

    const int tid = threadIdx.x;
    for (int i = tid; i < 2048; i += 128) {
        int ci = i >> 6, o = i & 63;
        w1n[ci * 64 + o] = w1[o * 32 + ci];
        float s = gm[o] * rsqrtf(vm[o] + EPS);
        wmn[ci * 64 + o] = wm[o * 32 + ci] * s;
    }
    for (int i = tid; i < 1024; i += 128) {
        int c = i >> 4, j = i & 15;
        wrn[c * 16 + j] = wr[j * 64 + c];
    }
    if (tid < 64) {
        float s = gm[tid] * rsqrtf(vm[tid] + EPS);
        tmv[tid] = s * bmap[tid] + betam[tid] - mm[tid] * s;
    }
    if (tid < 16) {
        float s = gr[tid] * rsqrtf(vr[tid] + EPS);
        srv[tid] = s; trv[tid] = br[tid] - mr[tid] * s;
    }
    __syncthreads();

    const int pg = blockIdx.x * 128 + tid;          // global pixel id
    const int b = pg >> 14, pix = pg & 16383;
    const float* xb = x + ((size_t)b << 19) + pix;

    float xv[32];
#pragma unroll
    for (int ci = 0; ci < 32; ci++) xv[ci] = __ldg(xb + ((size_t)ci << 14));

    // ---- conv1 + gelu, fused reduce accumulation ----
    u64 r[8];
#pragma unroll
    for (int q = 0; q < 8; q++) r[q] = 0ull;
    float* x1o = g_x1 + ((size_t)b << 20) + pix;
#pragma unroll
    for (int ob = 0; ob < 2; ob++) {                 // 2 blocks of 32 output ch
        u64 acc[16];
#pragma unroll
        for (int q = 0; q < 16; q++) acc[q] = 0ull;
#pragma unroll 4
        for (int ci = 0; ci < 32; ci++) {
            u64 xd = pack2(xv[ci], xv[ci]);
            const ulonglong2* wp = (const ulonglong2*)(w1n + ci * 64 + ob * 32);
#pragma unroll
            for (int q = 0; q < 8; q++) {
                ulonglong2 w = wp[q];                // (o,o+1),(o+2,o+3)
                acc[2 * q]     = fma2(w.x, xd, acc[2 * q]);
                acc[2 * q + 1] = fma2(w.y, xd, acc[2 * q + 1]);
            }
        }
#pragma unroll
        for (int lc = 0; lc < 16; lc++) {
            int c0 = ob * 32 + 2 * lc;
            float v0, v1; unpack2(acc[lc], v0, v1);
            float g0 = gelu1(v0), g1 = gelu1(v1);
            x1o[(size_t)c0 << 14]       = g0;
            x1o[(size_t)(c0 + 1) << 14] = g1;
            u64 g0d = pack2(g0, g0), g1d = pack2(g1, g1);
            const ulonglong2* r0 = (const ulonglong2*)(wrn + c0 * 16);
            const ulonglong2* r1 = (const ulonglong2*)(wrn + (c0 + 1) * 16);
#pragma unroll
            for (int q = 0; q < 4; q++) {
                ulonglong2 wA = r0[q];
                r[2 * q]     = fma2(wA.x, g0d, r[2 * q]);
                r[2 * q + 1] = fma2(wA.y, g0d, r[2 * q + 1]);
                ulonglong2 wB = r1[q];
                r[2 * q]     = fma2(wB.x, g1d, r[2 * q]);
                r[2 * q + 1] = fma2(wB.y, g1d, r[2 * q + 1]);
            }
        }
    }
    // ---- bn + relu on r -> g_r ----
    float* ro = g_r + (((size_t)b * 16) << 14) + pix;
#pragma unroll
    for (int q = 0; q < 8; q++) {
        float a0, a1; unpack2(r[q], a0, a1);
        ro[(size_t)(2 * q) << 14]     = fmaxf(fmaf(srv[2 * q],     a0, trv[2 * q]),     0.f);
        ro[(size_t)(2 * q + 1) << 14] = fmaxf(fmaf(srv[2 * q + 1], a1, trv[2 * q + 1]), 0.f);
    }

    // ---- mapping skip (bn folded) ----
    float* sko = g_skip + ((size_t)b << 20) + pix;
#pragma unroll
    for (int ob = 0; ob < 2; ob++) {
        u64 acc[16];
        const ulonglong2* tp = (const ulonglong2*)(tmv + ob * 32);
#pragma unroll
        for (int q = 0; q < 8; q++) { ulonglong2 t = tp[q]; acc[2 * q] = t.x; acc[2 * q + 1] = t.y; }
#pragma unroll 4
        for (int ci = 0; ci < 32; ci++) {
            u64 xd = pack2(xv[ci], xv[ci]);
            const ulonglong2* wp = (const ulonglong2*)(wmn + ci * 64 + ob * 32);
#pragma unroll
            for (int q = 0; q < 8; q++) {
                ulonglong2 w = wp[q];
                acc[2 * q]     = fma2(w.x, xd, acc[2 * q]);
                acc[2 * q + 1] = fma2(w.y, xd, acc[2 * q + 1]);
            }
        }
#pragma unroll
        for (int lc = 0; lc < 16; lc++) {
            int c0 = ob * 32 + 2 * lc;
            float s0, s1; unpack2(acc[lc], s0, s1);
            sko[(size_t)c0 << 14]       = s0;
            sko[(size_t)(c0 + 1) << 14] = s1;
        }
    }
}

// ===========================================================================
// Kernel 2 (R11): span-weight generation (in-tile, from g_r) + involution +
// BN1 + GELU + conv2(BN2 folded) + skip + GELU.
// Tile 16x8. 512 threads: thread = (pixel p 0..127, group g 0..3). 2 CTAs/SM.
// ws lives in smem as [g][di][j][8] (slot 7 zero-padded) -> every load is an
// aligned broadcast LDS.128. Per-di JIT weight computation: only 8 weight
// regs live at once.
// ===========================================================================
#define TW 16
#define TH 8
#define HW 22
#define HP 308           // 22*14 halo pixels
#define CSTR 68          // channel stride (17x16B => conflict-free LDS.128)
#define KM_X1S 0
#define KM_W2T (HP * CSTR)            // 20944, size 4096  [c][o] * bn2 scale
#define KM_WSS (KM_W2T + 4096)        // 25040, size 3584  [g][di][j][8]
#define KM_S1V (KM_WSS + 3584)        // 28624
#define KM_T1V (KM_S1V + 64)
#define KM_T2V (KM_T1V + 64)
#define KM_FLOATS (KM_T2V + 64)       // 28816
#define KM_BYTES (KM_FLOATS * 4)      // 115264 (x2 CTAs = 230.5KB < 233.5KB)

__global__ void __launch_bounds__(512, 2) k_main(
    const float* __restrict__ ws, const float* __restrict__ bs,
    const float* __restrict__ g1, const float* __restrict__ b1,
    const float* __restrict__ m1, const float* __restrict__ v1,
    const float* __restrict__ w2, const float* __restrict__ g2,
    const float* __restrict__ b2, const float* __restrict__ m2,
    const float* __restrict__ v2, float* __restrict__ out)
{
    float* x1s = smem + KM_X1S;
    float* w2t = smem + KM_W2T;
    float* wss = smem + KM_WSS;
    float* s1v = smem + KM_S1V;
    float* t1v = smem + KM_T1V;
    float* t2v = smem + KM_T2V;

    const int tid = threadIdx.x;
    const int b = blockIdx.z;
    const int tx0 = blockIdx.x * TW, ty0 = blockIdx.y * TH;

    for (int i = tid; i < 4096; i += 512) {
        int c = i >> 6, o = i & 63;
        float s2 = g2[o] * rsqrtf(v2[o] + EPS);
        w2t[c * 64 + o] = w2[o * 64 + c] * s2;      // [c][o], NOT duplicated
    }
    // wss[((gq*7+di)*16+j)*8+dj] = ws[(gq*49+di*7+dj)*16+j], dj==7 -> 0
    for (int i = tid; i < 3584; i += 512) {
        int dj = i & 7, j = (i >> 3) & 15, gd = i >> 7;   // gd = gq*7+di
        int di = gd % 7, gq = gd / 7;
        wss[i] = (dj < 7) ? ws[(gq * 49 + di * 7 + dj) * 16 + j] : 0.f;
    }
    if (tid < 64) {
        float s1 = g1[tid] * rsqrtf(v1[tid] + EPS);
        s1v[tid] = s1; t1v[tid] = b1[tid] - m1[tid] * s1;
        float s2 = g2[tid] * rsqrtf(v2[tid] + EPS);
        t2v[tid] = b2[tid] - m2[tid] * s2;
    }

    // halo load (zero padded): layout [halo_pixel][channel], stride CSTR
    const float* x1b = g_x1 + ((size_t)b << 20);
    for (int i = tid; i < HP * 64; i += 512) {
        int c = i / HP, hp = i - c * HP;
        int hy = hp / HW, hx = hp - hy * HW;
        int gy = ty0 - 3 + hy, gx = tx0 - 3 + hx;
        float v = 0.f;
        if (gy >= 0 && gy < 128 && gx >= 0 && gx < 128)
            v = __ldg(x1b + ((size_t)c << 14) + (gy << 7) + gx);
        x1s[hp * CSTR + c] = v;
    }
    __syncthreads();

    const int p = tid & 127, g = tid >> 7;
    const int py = p >> 4, px = p & 15;
    const int gy = ty0 + py, gx = tx0 + px;
    const int pix = (gy << 7) + gx;
    const int ch0 = g * 16;

    // ---- load reduce vector r (16 scalars, coalesced) ----
    float r16[16];
    const float* rb = g_r + (((size_t)b * 16) << 14) + pix;
#pragma unroll
    for (int j = 0; j < 16; j++) r16[j] = __ldg(rb + ((size_t)j << 14));

    // ---- involution with JIT weight generation per kernel row ----
    u64 acc[8];
#pragma unroll
    for (int q = 0; q < 8; q++) acc[q] = 0ull;
#pragma unroll
    for (int di = 0; di < 7; di++) {
        // weights for this row: w[dj] = bs[g*49+di*7+dj] + sum_j ws*r
        const float* bsp = bs + g * 49 + di * 7;     // warp-uniform -> L1 broadcast
        u64 wa[4];
        wa[0] = pack2(__ldg(bsp + 0), __ldg(bsp + 1));
        wa[1] = pack2(__ldg(bsp + 2), __ldg(bsp + 3));
        wa[2] = pack2(__ldg(bsp + 4), __ldg(bsp + 5));
        wa[3] = pack2(__ldg(bsp + 6), 0.f);
        const ulonglong2* wsp = (const ulonglong2*)(wss + ((g * 7 + di) * 16) * 8);
#pragma unroll
        for (int j = 0; j < 16; j++) {
            u64 rd = pack2(r16[j], r16[j]);
            ulonglong2 wA = wsp[2 * j];
            ulonglong2 wB = wsp[2 * j + 1];
            wa[0] = fma2(wA.x, rd, wa[0]);
            wa[1] = fma2(wA.y, rd, wa[1]);
            wa[2] = fma2(wB.x, rd, wa[2]);
            wa[3] = fma2(wB.y, rd, wa[3]);
        }
        float w7[8];
        unpack2(wa[0], w7[0], w7[1]); unpack2(wa[1], w7[2], w7[3]);
        unpack2(wa[2], w7[4], w7[5]); unpack2(wa[3], w7[6], w7[7]);

        const float* rowb = x1s + ((py + di) * HW + px) * CSTR + ch0;
#pragma unroll
        for (int dj = 0; dj < 7; dj++) {
            u64 kp = pack2(w7[dj], w7[dj]);
            const ulonglong2* xp = (const ulonglong2*)(rowb + dj * CSTR);
#pragma unroll
            for (int q = 0; q < 4; q++) {
                ulonglong2 xv = xp[q];
                acc[2 * q]     = fma2(kp, xv.x, acc[2 * q]);
                acc[2 * q + 1] = fma2(kp, xv.y, acc[2 * q + 1]);
            }
        }
    }
    // BN1 + GELU
    float y[16];
#pragma unroll
    for (int q = 0; q < 8; q++) {
        u64 s = *(const u64*)(s1v + ch0 + 2 * q);
        u64 t = *(const u64*)(t1v + ch0 + 2 * q);
        u64 v = fma2(acc[q], s, t);
        float a0, a1; unpack2(v, a0, a1);
        y[2 * q] = gelu1(a0); y[2 * q + 1] = gelu1(a1);
    }

    // ---- exchange y through smem (reuse halo region rows 0..127) ----
    __syncthreads();
#pragma unroll
    for (int c = 0; c < 16; c++) x1s[p * CSTR + ch0 + c] = y[c];
    __syncthreads();

    // ---- conv2 (bn2 folded): thread computes outs [ch0, ch0+16) ----
    u64 acc2[8];
#pragma unroll
    for (int q = 0; q < 8; q++) acc2[q] = *(const u64*)(t2v + ch0 + 2 * q);
    const float4* yb = (const float4*)(x1s + p * CSTR);
#pragma unroll 4
    for (int c4 = 0; c4 < 16; c4++) {
        float4 yv = yb[c4];
        float ya[4] = { yv.x, yv.y, yv.z, yv.w };
#pragma unroll
        for (int cc = 0; cc < 4; cc++) {
            int c = c4 * 4 + cc;
            u64 yp2 = pack2(ya[cc], ya[cc]);
            const ulonglong2* wp = (const ulonglong2*)(w2t + c * 64 + ch0);
#pragma unroll
            for (int q = 0; q < 4; q++) {
                ulonglong2 w = wp[q];                // w.x=(o,o+1), w.y=(o+2,o+3)
                acc2[2 * q]     = fma2(w.x, yp2, acc2[2 * q]);
                acc2[2 * q + 1] = fma2(w.y, yp2, acc2[2 * q + 1]);
            }
        }
    }
    // ---- + skip, GELU, store ----
    const float* skb = g_skip + ((size_t)b << 20) + pix;
    float* ob = out + ((size_t)b << 20) + pix;
#pragma unroll
    for (int q = 0; q < 8; q++) {
        float a0, a1; unpack2(acc2[q], a0, a1);
        int o0 = ch0 + 2 * q;
        a0 += __ldg(skb + ((size_t)o0 << 14));
        a1 += __ldg(skb + ((size_t)(o0 + 1) << 14));
        ob[(size_t)o0 << 14]       = gelu1(a0);
        ob[(size_t)(o0 + 1) << 14] = gelu1(a1);
    }
}

// ===========================================================================
// Launch. Input order: x w1 wr gr br mr vr ws bs g1 b1 m1 v1
//                      w2 g2 b2 m2 v2 wm bmap gm betam mm vm
// ===========================================================================
extern "C" void kernel_launch(void* const* d_in, const int* in_sizes, int n_in,
                              void* d_out, int out_size)
{
    (void)in_sizes; (void)n_in; (void)out_size;
    const float* x     = (const float*)d_in[0];
    const float* w1    = (const float*)d_in[1];
    const float* wr    = (const float*)d_in[2];
    const float* gr    = (const float*)d_in[3];
    const float* br    = (const float*)d_in[4];
    const float* mr    = (const float*)d_in[5];
    const float* vr    = (const float*)d_in[6];
    const float* ws    = (const float*)d_in[7];
    const float* bs    = (const float*)d_in[8];
    const float* g1    = (const float*)d_in[9];
    const float* b1    = (const float*)d_in[10];
    const float* m1    = (const float*)d_in[11];
    const float* v1    = (const float*)d_in[12];
    const float* w2    = (const float*)d_in[13];
    const float* g2    = (const float*)d_in[14];
    const float* b2    = (const float*)d_in[15];
    const float* m2    = (const float*)d_in[16];
    const float* v2    = (const float*)d_in[17];
    const float* wm    = (const float*)d_in[18];
    const float* bmap  = (const float*)d_in[19];
    const float* gm    = (const float*)d_in[20];
    const float* betam = (const float*)d_in[21];
    const float* mm    = (const float*)d_in[22];
    const float* vm    = (const float*)d_in[23];
    float* out = (float*)d_out;

    cudaFuncSetAttribute(k_pre,  cudaFuncAttributeMaxDynamicSharedMemorySize, KP_BYTES);
    cudaFuncSetAttribute(k_main, cudaFuncAttributeMaxDynamicSharedMemorySize, KM_BYTES);

    k_pre<<<512, 128, KP_BYTES>>>(x, w1, wr, gr, br, mr, vr,
                                  wm, bmap, gm, betam, mm, vm);
    k_main<<<dim3(128 / TW, 128 / TH, 4), 512, KM_BYTES>>>(
        ws, bs, g1, b1, m1, v1, w2, g2, b2, m2, v2, out);
}

// round 12
// speedup vs baseline: 1.7257x; 1.0017x over previous
#include <cuda_runtime.h>
#include <math.h>

#define EPS 1e-5f
typedef unsigned long long u64;

// ---------------- scratch (allocation forbidden -> __device__ globals) ----
__device__ float g_x1[4u * 64u * 128u * 128u];     // gelu(conv1(x))   16.8 MB
__device__ float g_skip[4u * 64u * 128u * 128u];   // bn(mapping(x))   16.8 MB
__device__ float g_r[4u * 16u * 128u * 128u];      // relu(bn(reduce))  4.2 MB

// ---------------- f32x2 helpers ----------------
__device__ __forceinline__ u64 pack2(float a, float b) {
    u64 r; asm("mov.b64 %0,{%1,%2};" : "=l"(r) : "f"(a), "f"(b)); return r;
}
__device__ __forceinline__ void unpack2(u64 v, float &a, float &b) {
    asm("mov.b64 {%0,%1},%2;" : "=f"(a), "=f"(b) : "l"(v));
}
__device__ __forceinline__ u64 fma2(u64 a, u64 b, u64 c) {
    u64 d; asm("fma.rn.f32x2 %0,%1,%2,%3;" : "=l"(d) : "l"(a), "l"(b), "l"(c)); return d;
}

// ---------------- fast exact-erf GELU (A&S 7.1.26, |erf err| < 1.5e-7) ----
// ~12 instr branch-free vs libm erff's ~25-40 with branches.
__device__ __forceinline__ float gelu1(float v) {
    float ax = fabsf(v) * 0.70710678118654752440f;   // |v|/sqrt(2)
    float d  = fmaf(0.3275911f, ax, 1.0f);
    float t; asm("rcp.approx.f32 %0,%1;" : "=f"(t) : "f"(d));
    float p = fmaf(1.061405429f, t, -1.453152027f);
    p = fmaf(p, t, 1.421413741f);
    p = fmaf(p, t, -0.284496736f);
    p = fmaf(p, t, 0.254829592f);
    p = p * t;
    float e = __expf(-ax * ax);                      // MUFU.EX2 path
    float er = fmaf(-p, e, 1.0f);                    // erf(|v|/sqrt2)
    er = copysignf(er, v);
    return 0.5f * v * (1.0f + er);
}

// ===========================================================================
// Kernel 1 (R11 structure): ONE PIXEL per thread, f32x2 lanes = CHANNEL pairs.
//   x1 = gelu(w1@x);  r = relu(bn(wr@x1)) -> g_r;  skip = bn(wm@x+b)
// ===========================================================================
#define KP_W1N 0        // 2048  [ci][o]
#define KP_WMN 2048     // 2048  [ci][o] (bn folded)
#define KP_WRN 4096     // 1024  [c][j]
#define KP_TM  5120     // 64    skip bias (bn folded)
#define KP_SRV 5184     // 16
#define KP_TRV 5200     // 16
#define KP_FLOATS 5216
#define KP_BYTES (KP_FLOATS * 4)

extern __shared__ __align__(16) float smem[];

__global__ void __launch_bounds__(128, 3) k_pre(
    const float* __restrict__ x,  const float* __restrict__ w1,
    const float* __restrict__ wr, const float* __restrict__ gr,
    const float* __restrict__ br, const float* __restrict__ mr,
    const float* __restrict__ vr, const float* __restrict__ wm,
    const float* __restrict__ bmap, const float* __restrict__ gm,
    const float* __restrict__ betam, const float* __restrict__ mm,
    const float* __restrict__ vm)
{
    float* w1n = smem + KP_W1N;
    float* wmn = smem + KP_WMN;
    float* wrn = smem + KP_WRN;
    float* tmv = smem + KP_TM;
    float* srv = smem + KP_SRV;
    float* trv = smem + KP_TRV;

    const int tid = threadIdx.x;
    for (int i = tid; i < 2048; i += 128) {
        int ci = i >> 6, o = i & 63;
        w1n[ci * 64 + o] = w1[o * 32 + ci];
        float s = gm[o] * rsqrtf(vm[o] + EPS);
        wmn[ci * 64 + o] = wm[o * 32 + ci] * s;
    }
    for (int i = tid; i < 1024; i += 128) {
        int c = i >> 4, j = i & 15;
        wrn[c * 16 + j] = wr[j * 64 + c];
    }
    if (tid < 64) {
        float s = gm[tid] * rsqrtf(vm[tid] + EPS);
        tmv[tid] = s * bmap[tid] + betam[tid] - mm[tid] * s;
    }
    if (tid < 16) {
        float s = gr[tid] * rsqrtf(vr[tid] + EPS);
        srv[tid] = s; trv[tid] = br[tid] - mr[tid] * s;
    }
    __syncthreads();

    const int pg = blockIdx.x * 128 + tid;          // global pixel id
    const int b = pg >> 14, pix = pg & 16383;
    const float* xb = x + ((size_t)b << 19) + pix;

    float xv[32];
#pragma unroll
    for (int ci = 0; ci < 32; ci++) xv[ci] = __ldg(xb + ((size_t)ci << 14));

    // ---- conv1 + gelu, fused reduce accumulation ----
    u64 r[8];
#pragma unroll
    for (int q = 0; q < 8; q++) r[q] = 0ull;
    float* x1o = g_x1 + ((size_t)b << 20) + pix;
#pragma unroll
    for (int ob = 0; ob < 2; ob++) {                 // 2 blocks of 32 output ch
        u64 acc[16];
#pragma unroll
        for (int q = 0; q < 16; q++) acc[q] = 0ull;
#pragma unroll 4
        for (int ci = 0; ci < 32; ci++) {
            u64 xd = pack2(xv[ci], xv[ci]);
            const ulonglong2* wp = (const ulonglong2*)(w1n + ci * 64 + ob * 32);
#pragma unroll
            for (int q = 0; q < 8; q++) {
                ulonglong2 w = wp[q];                // (o,o+1),(o+2,o+3)
                acc[2 * q]     = fma2(w.x, xd, acc[2 * q]);
                acc[2 * q + 1] = fma2(w.y, xd, acc[2 * q + 1]);
            }
        }
#pragma unroll
        for (int lc = 0; lc < 16; lc++) {
            int c0 = ob * 32 + 2 * lc;
            float v0, v1; unpack2(acc[lc], v0, v1);
            float g0 = gelu1(v0), g1 = gelu1(v1);
            x1o[(size_t)c0 << 14]       = g0;
            x1o[(size_t)(c0 + 1) << 14] = g1;
            u64 g0d = pack2(g0, g0), g1d = pack2(g1, g1);
            const ulonglong2* r0 = (const ulonglong2*)(wrn + c0 * 16);
            const ulonglong2* r1 = (const ulonglong2*)(wrn + (c0 + 1) * 16);
#pragma unroll
            for (int q = 0; q < 4; q++) {
                ulonglong2 wA = r0[q];
                r[2 * q]     = fma2(wA.x, g0d, r[2 * q]);
                r[2 * q + 1] = fma2(wA.y, g0d, r[2 * q + 1]);
                ulonglong2 wB = r1[q];
                r[2 * q]     = fma2(wB.x, g1d, r[2 * q]);
                r[2 * q + 1] = fma2(wB.y, g1d, r[2 * q + 1]);
            }
        }
    }
    // ---- bn + relu on r -> g_r ----
    float* ro = g_r + (((size_t)b * 16) << 14) + pix;
#pragma unroll
    for (int q = 0; q < 8; q++) {
        float a0, a1; unpack2(r[q], a0, a1);
        ro[(size_t)(2 * q) << 14]     = fmaxf(fmaf(srv[2 * q],     a0, trv[2 * q]),     0.f);
        ro[(size_t)(2 * q + 1) << 14] = fmaxf(fmaf(srv[2 * q + 1], a1, trv[2 * q + 1]), 0.f);
    }

    // ---- mapping skip (bn folded) ----
    float* sko = g_skip + ((size_t)b << 20) + pix;
#pragma unroll
    for (int ob = 0; ob < 2; ob++) {
        u64 acc[16];
        const ulonglong2* tp = (const ulonglong2*)(tmv + ob * 32);
#pragma unroll
        for (int q = 0; q < 8; q++) { ulonglong2 t = tp[q]; acc[2 * q] = t.x; acc[2 * q + 1] = t.y; }
#pragma unroll 4
        for (int ci = 0; ci < 32; ci++) {
            u64 xd = pack2(xv[ci], xv[ci]);
            const ulonglong2* wp = (const ulonglong2*)(wmn + ci * 64 + ob * 32);
#pragma unroll
            for (int q = 0; q < 8; q++) {
                ulonglong2 w = wp[q];
                acc[2 * q]     = fma2(w.x, xd, acc[2 * q]);
                acc[2 * q + 1] = fma2(w.y, xd, acc[2 * q + 1]);
            }
        }
#pragma unroll
        for (int lc = 0; lc < 16; lc++) {
            int c0 = ob * 32 + 2 * lc;
            float s0, s1; unpack2(acc[lc], s0, s1);
            sko[(size_t)c0 << 14]       = s0;
            sko[(size_t)(c0 + 1) << 14] = s1;
        }
    }
}

// ===========================================================================
// Kernel 2 (R11 structure): span-weight JIT (from g_r) + involution + BN1 +
// GELU + conv2(BN2 folded) + skip + GELU.
// Tile 16x8. 512 threads: thread = (pixel p 0..127, group g 0..3). 2 CTAs/SM.
// ===========================================================================
#define TW 16
#define TH 8
#define HW 22
#define HP 308           // 22*14 halo pixels
#define CSTR 68          // channel stride (17x16B => conflict-free LDS.128)
#define KM_X1S 0
#define KM_W2T (HP * CSTR)            // 20944, size 4096  [c][o] * bn2 scale
#define KM_WSS (KM_W2T + 4096)        // 25040, size 3584  [g][di][j][8]
#define KM_S1V (KM_WSS + 3584)        // 28624
#define KM_T1V (KM_S1V + 64)
#define KM_T2V (KM_T1V + 64)
#define KM_FLOATS (KM_T2V + 64)       // 28816
#define KM_BYTES (KM_FLOATS * 4)      // 115264 (x2 CTAs fits)

__global__ void __launch_bounds__(512, 2) k_main(
    const float* __restrict__ ws, const float* __restrict__ bs,
    const float* __restrict__ g1, const float* __restrict__ b1,
    const float* __restrict__ m1, const float* __restrict__ v1,
    const float* __restrict__ w2, const float* __restrict__ g2,
    const float* __restrict__ b2, const float* __restrict__ m2,
    const float* __restrict__ v2, float* __restrict__ out)
{
    float* x1s = smem + KM_X1S;
    float* w2t = smem + KM_W2T;
    float* wss = smem + KM_WSS;
    float* s1v = smem + KM_S1V;
    float* t1v = smem + KM_T1V;
    float* t2v = smem + KM_T2V;

    const int tid = threadIdx.x;
    const int b = blockIdx.z;
    const int tx0 = blockIdx.x * TW, ty0 = blockIdx.y * TH;

    for (int i = tid; i < 4096; i += 512) {
        int c = i >> 6, o = i & 63;
        float s2 = g2[o] * rsqrtf(v2[o] + EPS);
        w2t[c * 64 + o] = w2[o * 64 + c] * s2;      // [c][o], NOT duplicated
    }
    // wss[((gq*7+di)*16+j)*8+dj] = ws[(gq*49+di*7+dj)*16+j], dj==7 -> 0
    for (int i = tid; i < 3584; i += 512) {
        int dj = i & 7, j = (i >> 3) & 15, gd = i >> 7;   // gd = gq*7+di
        int di = gd % 7, gq = gd / 7;
        wss[i] = (dj < 7) ? ws[(gq * 49 + di * 7 + dj) * 16 + j] : 0.f;
    }
    if (tid < 64) {
        float s1 = g1[tid] * rsqrtf(v1[tid] + EPS);
        s1v[tid] = s1; t1v[tid] = b1[tid] - m1[tid] * s1;
        float s2 = g2[tid] * rsqrtf(v2[tid] + EPS);
        t2v[tid] = b2[tid] - m2[tid] * s2;
    }

    // halo load (zero padded): layout [halo_pixel][channel], stride CSTR
    const float* x1b = g_x1 + ((size_t)b << 20);
    for (int i = tid; i < HP * 64; i += 512) {
        int c = i / HP, hp = i - c * HP;
        int hy = hp / HW, hx = hp - hy * HW;
        int gy = ty0 - 3 + hy, gx = tx0 - 3 + hx;
        float v = 0.f;
        if (gy >= 0 && gy < 128 && gx >= 0 && gx < 128)
            v = __ldg(x1b + ((size_t)c << 14) + (gy << 7) + gx);
        x1s[hp * CSTR + c] = v;
    }
    __syncthreads();

    const int p = tid & 127, g = tid >> 7;
    const int py = p >> 4, px = p & 15;
    const int gy = ty0 + py, gx = tx0 + px;
    const int pix = (gy << 7) + gx;
    const int ch0 = g * 16;

    // ---- load reduce vector r (16 scalars, coalesced) ----
    float r16[16];
    const float* rb = g_r + (((size_t)b * 16) << 14) + pix;
#pragma unroll
    for (int j = 0; j < 16; j++) r16[j] = __ldg(rb + ((size_t)j << 14));

    // ---- involution with JIT weight generation per kernel row ----
    u64 acc[8];
#pragma unroll
    for (int q = 0; q < 8; q++) acc[q] = 0ull;
#pragma unroll
    for (int di = 0; di < 7; di++) {
        // weights for this row: w[dj] = bs[g*49+di*7+dj] + sum_j ws*r
        const float* bsp = bs + g * 49 + di * 7;     // warp-uniform -> L1 broadcast
        u64 wa[4];
        wa[0] = pack2(__ldg(bsp + 0), __ldg(bsp + 1));
        wa[1] = pack2(__ldg(bsp + 2), __ldg(bsp + 3));
        wa[2] = pack2(__ldg(bsp + 4), __ldg(bsp + 5));
        wa[3] = pack2(__ldg(bsp + 6), 0.f);
        const ulonglong2* wsp = (const ulonglong2*)(wss + ((g * 7 + di) * 16) * 8);
#pragma unroll
        for (int j = 0; j < 16; j++) {
            u64 rd = pack2(r16[j], r16[j]);
            ulonglong2 wA = wsp[2 * j];
            ulonglong2 wB = wsp[2 * j + 1];
            wa[0] = fma2(wA.x, rd, wa[0]);
            wa[1] = fma2(wA.y, rd, wa[1]);
            wa[2] = fma2(wB.x, rd, wa[2]);
            wa[3] = fma2(wB.y, rd, wa[3]);
        }
        float w7[8];
        unpack2(wa[0], w7[0], w7[1]); unpack2(wa[1], w7[2], w7[3]);
        unpack2(wa[2], w7[4], w7[5]); unpack2(wa[3], w7[6], w7[7]);

        const float* rowb = x1s + ((py + di) * HW + px) * CSTR + ch0;
#pragma unroll
        for (int dj = 0; dj < 7; dj++) {
            u64 kp = pack2(w7[dj], w7[dj]);
            const ulonglong2* xp = (const ulonglong2*)(rowb + dj * CSTR);
#pragma unroll
            for (int q = 0; q < 4; q++) {
                ulonglong2 xv = xp[q];
                acc[2 * q]     = fma2(kp, xv.x, acc[2 * q]);
                acc[2 * q + 1] = fma2(kp, xv.y, acc[2 * q + 1]);
            }
        }
    }
    // BN1 + GELU
    float y[16];
#pragma unroll
    for (int q = 0; q < 8; q++) {
        u64 s = *(const u64*)(s1v + ch0 + 2 * q);
        u64 t = *(const u64*)(t1v + ch0 + 2 * q);
        u64 v = fma2(acc[q], s, t);
        float a0, a1; unpack2(v, a0, a1);
        y[2 * q] = gelu1(a0); y[2 * q + 1] = gelu1(a1);
    }

    // ---- exchange y through smem (reuse halo region rows 0..127) ----
    __syncthreads();
#pragma unroll
    for (int c = 0; c < 16; c++) x1s[p * CSTR + ch0 + c] = y[c];
    __syncthreads();

    // ---- conv2 (bn2 folded): thread computes outs [ch0, ch0+16) ----
    u64 acc2[8];
#pragma unroll
    for (int q = 0; q < 8; q++) acc2[q] = *(const u64*)(t2v + ch0 + 2 * q);
    const float4* yb = (const float4*)(x1s + p * CSTR);
#pragma unroll 4
    for (int c4 = 0; c4 < 16; c4++) {
        float4 yv = yb[c4];
        float ya[4] = { yv.x, yv.y, yv.z, yv.w };
#pragma unroll
        for (int cc = 0; cc < 4; cc++) {
            int c = c4 * 4 + cc;
            u64 yp2 = pack2(ya[cc], ya[cc]);
            const ulonglong2* wp = (const ulonglong2*)(w2t + c * 64 + ch0);
#pragma unroll
            for (int q = 0; q < 4; q++) {
                ulonglong2 w = wp[q];                // w.x=(o,o+1), w.y=(o+2,o+3)
                acc2[2 * q]     = fma2(w.x, yp2, acc2[2 * q]);
                acc2[2 * q + 1] = fma2(w.y, yp2, acc2[2 * q + 1]);
            }
        }
    }
    // ---- + skip, GELU, store ----
    const float* skb = g_skip + ((size_t)b << 20) + pix;
    float* ob = out + ((size_t)b << 20) + pix;
#pragma unroll
    for (int q = 0; q < 8; q++) {
        float a0, a1; unpack2(acc2[q], a0, a1);
        int o0 = ch0 + 2 * q;
        a0 += __ldg(skb + ((size_t)o0 << 14));
        a1 += __ldg(skb + ((size_t)(o0 + 1) << 14));
        ob[(size_t)o0 << 14]       = gelu1(a0);
        ob[(size_t)(o0 + 1) << 14] = gelu1(a1);
    }
}

// ===========================================================================
// Launch. Input order: x w1 wr gr br mr vr ws bs g1 b1 m1 v1
//                      w2 g2 b2 m2 v2 wm bmap gm betam mm vm
// ===========================================================================
extern "C" void kernel_launch(void* const* d_in, const int* in_sizes, int n_in,
                              void* d_out, int out_size)
{
    (void)in_sizes; (void)n_in; (void)out_size;
    const float* x     = (const float*)d_in[0];
    const float* w1    = (const float*)d_in[1];
    const float* wr    = (const float*)d_in[2];
    const float* gr    = (const float*)d_in[3];
    const float* br    = (const float*)d_in[4];
    const float* mr    = (const float*)d_in[5];
    const float* vr    = (const float*)d_in[6];
    const float* ws    = (const float*)d_in[7];
    const float* bs    = (const float*)d_in[8];
    const float* g1    = (const float*)d_in[9];
    const float* b1    = (const float*)d_in[10];
    const float* m1    = (const float*)d_in[11];
    const float* v1    = (const float*)d_in[12];
    const float* w2    = (const float*)d_in[13];
    const float* g2    = (const float*)d_in[14];
    const float* b2    = (const float*)d_in[15];
    const float* m2    = (const float*)d_in[16];
    const float* v2    = (const float*)d_in[17];
    const float* wm    = (const float*)d_in[18];
    const float* bmap  = (const float*)d_in[19];
    const float* gm    = (const float*)d_in[20];
    const float* betam = (const float*)d_in[21];
    const float* mm    = (const float*)d_in[22];
    const float* vm    = (const float*)d_in[23];
    float* out = (float*)d_out;

    cudaFuncSetAttribute(k_pre,  cudaFuncAttributeMaxDynamicSharedMemorySize, KP_BYTES);
    cudaFuncSetAttribute(k_main, cudaFuncAttributeMaxDynamicSharedMemorySize, KM_BYTES);

    k_pre<<<512, 128, KP_BYTES>>>(x, w1, wr, gr, br, mr, vr,
                                  wm, bmap, gm, betam, mm, vm);
    k_main<<<dim3(128 / TW, 128 / TH, 4), 512, KM_BYTES>>>(
        ws, bs, g1, b1, m1, v1, w2, g2, b2, m2, v2, out);
}

// round 13
// speedup vs baseline: 1.7347x; 1.0052x over previous
#include <cuda_runtime.h>
#include <math.h>

#define EPS 1e-5f
typedef unsigned long long u64;

// ---------------- scratch (allocation forbidden -> __device__ globals) ----
__device__ float g_x1[4u * 64u * 128u * 128u];     // gelu(conv1(x))   16.8 MB
__device__ float g_skip[4u * 64u * 128u * 128u];   // bn(mapping(x))   16.8 MB
__device__ float g_r[4u * 16u * 128u * 128u];      // relu(bn(reduce))  4.2 MB

// ---------------- f32x2 helpers ----------------
__device__ __forceinline__ u64 pack2(float a, float b) {
    u64 r; asm("mov.b64 %0,{%1,%2};" : "=l"(r) : "f"(a), "f"(b)); return r;
}
__device__ __forceinline__ void unpack2(u64 v, float &a, float &b) {
    asm("mov.b64 {%0,%1},%2;" : "=f"(a), "=f"(b) : "l"(v));
}
__device__ __forceinline__ u64 fma2(u64 a, u64 b, u64 c) {
    u64 d; asm("fma.rn.f32x2 %0,%1,%2,%3;" : "=l"(d) : "l"(a), "l"(b), "l"(c)); return d;
}

// ---------------- fast exact-erf GELU (A&S 7.1.26, |erf err| < 1.5e-7) ----
// ~12 instr branch-free vs libm erff's ~25-40 with branches.
__device__ __forceinline__ float gelu1(float v) {
    float ax = fabsf(v) * 0.70710678118654752440f;   // |v|/sqrt(2)
    float d  = fmaf(0.3275911f, ax, 1.0f);
    float t; asm("rcp.approx.f32 %0,%1;" : "=f"(t) : "f"(d));
    float p = fmaf(1.061405429f, t, -1.453152027f);
    p = fmaf(p, t, 1.421413741f);
    p = fmaf(p, t, -0.284496736f);
    p = fmaf(p, t, 0.254829592f);
    p = p * t;
    float e = __expf(-ax * ax);                      // MUFU.EX2 path
    float er = fmaf(-p, e, 1.0f);                    // erf(|v|/sqrt2)
    er = copysignf(er, v);
    return 0.5f * v * (1.0f + er);
}

// ===========================================================================
// Kernel 1 (R11 structure): ONE PIXEL per thread, f32x2 lanes = CHANNEL pairs.
//   x1 = gelu(w1@x);  r = relu(bn(wr@x1)) -> g_r;  skip = bn(wm@x+b)
// ===========================================================================
#define KP_W1N 0        // 2048  [ci][o]
#define KP_WMN 2048     // 2048  [ci][o] (bn folded)
#define KP_WRN 4096     // 1024  [c][j]
#define KP_TM  5120     // 64    skip bias (bn folded)
#define KP_SRV 5184     // 16
#define KP_TRV 5200     // 16
#define KP_FLOATS 5216
#define KP_BYTES (KP_FLOATS * 4)

extern __shared__ __align__(16) float smem[];

__global__ void __launch_bounds__(128, 3) k_pre(
    const float* __restrict__ x,  const float* __restrict__ w1,
    const float* __restrict__ wr, const float* __restrict__ gr,
    const float* __restrict__ br, const float* __restrict__ mr,
    const float* __restrict__ vr, const float* __restrict__ wm,
    const float* __restrict__ bmap, const float* __restrict__ gm,
    const float* __restrict__ betam, const float* __restrict__ mm,
    const float* __restrict__ vm)
{
    float* w1n = smem + KP_W1N;
    float* wmn = smem + KP_WMN;
    float* wrn = smem + KP_WRN;
    float* tmv = smem + KP_TM;
    float* srv = smem + KP_SRV;
    float* trv = smem + KP_TRV;

    const int tid = threadIdx.x;
    for (int i = tid; i < 2048; i += 128) {
        int ci = i >> 6, o = i & 63;
        w1n[ci * 64 + o] = w1[o * 32 + ci];
        float s = gm[o] * rsqrtf(vm[o] + EPS);
        wmn[ci * 64 + o] = wm[o * 32 + ci] * s;
    }
    for (int i = tid; i < 1024; i += 128) {
        int c = i >> 4, j = i & 15;
        wrn[c * 16 + j] = wr[j * 64 + c];
    }
    if (tid < 64) {
        float s = gm[tid] * rsqrtf(vm[tid] + EPS);
        tmv[tid] = s * bmap[tid] + betam[tid] - mm[tid] * s;
    }
    if (tid < 16) {
        float s = gr[tid] * rsqrtf(vr[tid] + EPS);
        srv[tid] = s; trv[tid] = br[tid] - mr[tid] * s;
    }
    __syncthreads();

    const int pg = blockIdx.x * 128 + tid;          // global pixel id
    const int b = pg >> 14, pix = pg & 16383;
    const float* xb = x + ((size_t)b << 19) + pix;

    float xv[32];
#pragma unroll
    for (int ci = 0; ci < 32; ci++) xv[ci] = __ldg(xb + ((size_t)ci << 14));

    // ---- conv1 + gelu, fused reduce accumulation ----
    u64 r[8];
#pragma unroll
    for (int q = 0; q < 8; q++) r[q] = 0ull;
    float* x1o = g_x1 + ((size_t)b << 20) + pix;
#pragma unroll
    for (int ob = 0; ob < 2; ob++) {                 // 2 blocks of 32 output ch
        u64 acc[16];
#pragma unroll
        for (int q = 0; q < 16; q++) acc[q] = 0ull;
#pragma unroll 4
        for (int ci = 0; ci < 32; ci++) {
            u64 xd = pack2(xv[ci], xv[ci]);
            const ulonglong2* wp = (const ulonglong2*)(w1n + ci * 64 + ob * 32);
#pragma unroll
            for (int q = 0; q < 8; q++) {
                ulonglong2 w = wp[q];                // (o,o+1),(o+2,o+3)
                acc[2 * q]     = fma2(w.x, xd, acc[2 * q]);
                acc[2 * q + 1] = fma2(w.y, xd, acc[2 * q + 1]);
            }
        }
#pragma unroll
        for (int lc = 0; lc < 16; lc++) {
            int c0 = ob * 32 + 2 * lc;
            float v0, v1; unpack2(acc[lc], v0, v1);
            float g0 = gelu1(v0), g1 = gelu1(v1);
            x1o[(size_t)c0 << 14]       = g0;
            x1o[(size_t)(c0 + 1) << 14] = g1;
            u64 g0d = pack2(g0, g0), g1d = pack2(g1, g1);
            const ulonglong2* r0 = (const ulonglong2*)(wrn + c0 * 16);
            const ulonglong2* r1 = (const ulonglong2*)(wrn + (c0 + 1) * 16);
#pragma unroll
            for (int q = 0; q < 4; q++) {
                ulonglong2 wA = r0[q];
                r[2 * q]     = fma2(wA.x, g0d, r[2 * q]);
                r[2 * q + 1] = fma2(wA.y, g0d, r[2 * q + 1]);
                ulonglong2 wB = r1[q];
                r[2 * q]     = fma2(wB.x, g1d, r[2 * q]);
                r[2 * q + 1] = fma2(wB.y, g1d, r[2 * q + 1]);
            }
        }
    }
    // ---- bn + relu on r -> g_r ----
    float* ro = g_r + (((size_t)b * 16) << 14) + pix;
#pragma unroll
    for (int q = 0; q < 8; q++) {
        float a0, a1; unpack2(r[q], a0, a1);
        ro[(size_t)(2 * q) << 14]     = fmaxf(fmaf(srv[2 * q],     a0, trv[2 * q]),     0.f);
        ro[(size_t)(2 * q + 1) << 14] = fmaxf(fmaf(srv[2 * q + 1], a1, trv[2 * q + 1]), 0.f);
    }

    // ---- mapping skip (bn folded) ----
    float* sko = g_skip + ((size_t)b << 20) + pix;
#pragma unroll
    for (int ob = 0; ob < 2; ob++) {
        u64 acc[16];
        const ulonglong2* tp = (const ulonglong2*)(tmv + ob * 32);
#pragma unroll
        for (int q = 0; q < 8; q++) { ulonglong2 t = tp[q]; acc[2 * q] = t.x; acc[2 * q + 1] = t.y; }
#pragma unroll 4
        for (int ci = 0; ci < 32; ci++) {
            u64 xd = pack2(xv[ci], xv[ci]);
            const ulonglong2* wp = (const ulonglong2*)(wmn + ci * 64 + ob * 32);
#pragma unroll
            for (int q = 0; q < 8; q++) {
                ulonglong2 w = wp[q];
                acc[2 * q]     = fma2(w.x, xd, acc[2 * q]);
                acc[2 * q + 1] = fma2(w.y, xd, acc[2 * q + 1]);
            }
        }
#pragma unroll
        for (int lc = 0; lc < 16; lc++) {
            int c0 = ob * 32 + 2 * lc;
            float s0, s1; unpack2(acc[lc], s0, s1);
            sko[(size_t)c0 << 14]       = s0;
            sko[(size_t)(c0 + 1) << 14] = s1;
        }
    }
}

// ===========================================================================
// Kernel 2 (R11 structure): span-weight JIT (from g_r) + involution + BN1 +
// GELU + conv2(BN2 folded) + skip + GELU.
// Tile 16x8. 512 threads: thread = (pixel p 0..127, group g 0..3). 2 CTAs/SM.
// ===========================================================================
#define TW 16
#define TH 8
#define HW 22
#define HP 308           // 22*14 halo pixels
#define CSTR 68          // channel stride (17x16B => conflict-free LDS.128)
#define KM_X1S 0
#define KM_W2T (HP * CSTR)            // 20944, size 4096  [c][o] * bn2 scale
#define KM_WSS (KM_W2T + 4096)        // 25040, size 3584  [g][di][j][8]
#define KM_S1V (KM_WSS + 3584)        // 28624
#define KM_T1V (KM_S1V + 64)
#define KM_T2V (KM_T1V + 64)
#define KM_FLOATS (KM_T2V + 64)       // 28816
#define KM_BYTES (KM_FLOATS * 4)      // 115264 (x2 CTAs fits)

__global__ void __launch_bounds__(512, 2) k_main(
    const float* __restrict__ ws, const float* __restrict__ bs,
    const float* __restrict__ g1, const float* __restrict__ b1,
    const float* __restrict__ m1, const float* __restrict__ v1,
    const float* __restrict__ w2, const float* __restrict__ g2,
    const float* __restrict__ b2, const float* __restrict__ m2,
    const float* __restrict__ v2, float* __restrict__ out)
{
    float* x1s = smem + KM_X1S;
    float* w2t = smem + KM_W2T;
    float* wss = smem + KM_WSS;
    float* s1v = smem + KM_S1V;
    float* t1v = smem + KM_T1V;
    float* t2v = smem + KM_T2V;

    const int tid = threadIdx.x;
    const int b = blockIdx.z;
    const int tx0 = blockIdx.x * TW, ty0 = blockIdx.y * TH;

    for (int i = tid; i < 4096; i += 512) {
        int c = i >> 6, o = i & 63;
        float s2 = g2[o] * rsqrtf(v2[o] + EPS);
        w2t[c * 64 + o] = w2[o * 64 + c] * s2;      // [c][o], NOT duplicated
    }
    // wss[((gq*7+di)*16+j)*8+dj] = ws[(gq*49+di*7+dj)*16+j], dj==7 -> 0
    for (int i = tid; i < 3584; i += 512) {
        int dj = i & 7, j = (i >> 3) & 15, gd = i >> 7;   // gd = gq*7+di
        int di = gd % 7, gq = gd / 7;
        wss[i] = (dj < 7) ? ws[(gq * 49 + di * 7 + dj) * 16 + j] : 0.f;
    }
    if (tid < 64) {
        float s1 = g1[tid] * rsqrtf(v1[tid] + EPS);
        s1v[tid] = s1; t1v[tid] = b1[tid] - m1[tid] * s1;
        float s2 = g2[tid] * rsqrtf(v2[tid] + EPS);
        t2v[tid] = b2[tid] - m2[tid] * s2;
    }

    // halo load (zero padded): layout [halo_pixel][channel], stride CSTR
    const float* x1b = g_x1 + ((size_t)b << 20);
    for (int i = tid; i < HP * 64; i += 512) {
        int c = i / HP, hp = i - c * HP;
        int hy = hp / HW, hx = hp - hy * HW;
        int gy = ty0 - 3 + hy, gx = tx0 - 3 + hx;
        float v = 0.f;
        if (gy >= 0 && gy < 128 && gx >= 0 && gx < 128)
            v = __ldg(x1b + ((size_t)c << 14) + (gy << 7) + gx);
        x1s[hp * CSTR + c] = v;
    }
    __syncthreads();

    const int p = tid & 127, g = tid >> 7;
    const int py = p >> 4, px = p & 15;
    const int gy = ty0 + py, gx = tx0 + px;
    const int pix = (gy << 7) + gx;
    const int ch0 = g * 16;

    // ---- load reduce vector r (16 scalars, coalesced) ----
    float r16[16];
    const float* rb = g_r + (((size_t)b * 16) << 14) + pix;
#pragma unroll
    for (int j = 0; j < 16; j++) r16[j] = __ldg(rb + ((size_t)j << 14));

    // ---- involution with JIT weight generation per kernel row ----
    u64 acc[8];
#pragma unroll
    for (int q = 0; q < 8; q++) acc[q] = 0ull;
#pragma unroll
    for (int di = 0; di < 7; di++) {
        // weights for this row: w[dj] = bs[g*49+di*7+dj] + sum_j ws*r
        const float* bsp = bs + g * 49 + di * 7;     // warp-uniform -> L1 broadcast
        u64 wa[4];
        wa[0] = pack2(__ldg(bsp + 0), __ldg(bsp + 1));
        wa[1] = pack2(__ldg(bsp + 2), __ldg(bsp + 3));
        wa[2] = pack2(__ldg(bsp + 4), __ldg(bsp + 5));
        wa[3] = pack2(__ldg(bsp + 6), 0.f);
        const ulonglong2* wsp = (const ulonglong2*)(wss + ((g * 7 + di) * 16) * 8);
#pragma unroll
        for (int j = 0; j < 16; j++) {
            u64 rd = pack2(r16[j], r16[j]);
            ulonglong2 wA = wsp[2 * j];
            ulonglong2 wB = wsp[2 * j + 1];
            wa[0] = fma2(wA.x, rd, wa[0]);
            wa[1] = fma2(wA.y, rd, wa[1]);
            wa[2] = fma2(wB.x, rd, wa[2]);
            wa[3] = fma2(wB.y, rd, wa[3]);
        }
        float w7[8];
        unpack2(wa[0], w7[0], w7[1]); unpack2(wa[1], w7[2], w7[3]);
        unpack2(wa[2], w7[4], w7[5]); unpack2(wa[3], w7[6], w7[7]);

        const float* rowb = x1s + ((py + di) * HW + px) * CSTR + ch0;
#pragma unroll
        for (int dj = 0; dj < 7; dj++) {
            u64 kp = pack2(w7[dj], w7[dj]);
            const ulonglong2* xp = (const ulonglong2*)(rowb + dj * CSTR);
#pragma unroll
            for (int q = 0; q < 4; q++) {
                ulonglong2 xv = xp[q];
                acc[2 * q]     = fma2(kp, xv.x, acc[2 * q]);
                acc[2 * q + 1] = fma2(kp, xv.y, acc[2 * q + 1]);
            }
        }
    }
    // BN1 + GELU
    float y[16];
#pragma unroll
    for (int q = 0; q < 8; q++) {
        u64 s = *(const u64*)(s1v + ch0 + 2 * q);
        u64 t = *(const u64*)(t1v + ch0 + 2 * q);
        u64 v = fma2(acc[q], s, t);
        float a0, a1; unpack2(v, a0, a1);
        y[2 * q] = gelu1(a0); y[2 * q + 1] = gelu1(a1);
    }

    // ---- exchange y through smem (reuse halo region rows 0..127) ----
    __syncthreads();
#pragma unroll
    for (int c = 0; c < 16; c++) x1s[p * CSTR + ch0 + c] = y[c];
    __syncthreads();

    // ---- conv2 (bn2 folded): thread computes outs [ch0, ch0+16) ----
    u64 acc2[8];
#pragma unroll
    for (int q = 0; q < 8; q++) acc2[q] = *(const u64*)(t2v + ch0 + 2 * q);
    const float4* yb = (const float4*)(x1s + p * CSTR);
#pragma unroll 4
    for (int c4 = 0; c4 < 16; c4++) {
        float4 yv = yb[c4];
        float ya[4] = { yv.x, yv.y, yv.z, yv.w };
#pragma unroll
        for (int cc = 0; cc < 4; cc++) {
            int c = c4 * 4 + cc;
            u64 yp2 = pack2(ya[cc], ya[cc]);
            const ulonglong2* wp = (const ulonglong2*)(w2t + c * 64 + ch0);
#pragma unroll
            for (int q = 0; q < 4; q++) {
                ulonglong2 w = wp[q];                // w.x=(o,o+1), w.y=(o+2,o+3)
                acc2[2 * q]     = fma2(w.x, yp2, acc2[2 * q]);
                acc2[2 * q + 1] = fma2(w.y, yp2, acc2[2 * q + 1]);
            }
        }
    }
    // ---- + skip, GELU, store ----
    const float* skb = g_skip + ((size_t)b << 20) + pix;
    float* ob = out + ((size_t)b << 20) + pix;
#pragma unroll
    for (int q = 0; q < 8; q++) {
        float a0, a1; unpack2(acc2[q], a0, a1);
        int o0 = ch0 + 2 * q;
        a0 += __ldg(skb + ((size_t)o0 << 14));
        a1 += __ldg(skb + ((size_t)(o0 + 1) << 14));
        ob[(size_t)o0 << 14]       = gelu1(a0);
        ob[(size_t)(o0 + 1) << 14] = gelu1(a1);
    }
}

// ===========================================================================
// Launch. Input order: x w1 wr gr br mr vr ws bs g1 b1 m1 v1
//                      w2 g2 b2 m2 v2 wm bmap gm betam mm vm
// ===========================================================================
extern "C" void kernel_launch(void* const* d_in, const int* in_sizes, int n_in,
                              void* d_out, int out_size)
{
    (void)in_sizes; (void)n_in; (void)out_size;
    const float* x     = (const float*)d_in[0];
    const float* w1    = (const float*)d_in[1];
    const float* wr    = (const float*)d_in[2];
    const float* gr    = (const float*)d_in[3];
    const float* br    = (const float*)d_in[4];
    const float* mr    = (const float*)d_in[5];
    const float* vr    = (const float*)d_in[6];
    const float* ws    = (const float*)d_in[7];
    const float* bs    = (const float*)d_in[8];
    const float* g1    = (const float*)d_in[9];
    const float* b1    = (const float*)d_in[10];
    const float* m1    = (const float*)d_in[11];
    const float* v1    = (const float*)d_in[12];
    const float* w2    = (const float*)d_in[13];
    const float* g2    = (const float*)d_in[14];
    const float* b2    = (const float*)d_in[15];
    const float* m2    = (const float*)d_in[16];
    const float* v2    = (const float*)d_in[17];
    const float* wm    = (const float*)d_in[18];
    const float* bmap  = (const float*)d_in[19];
    const float* gm    = (const float*)d_in[20];
    const float* betam = (const float*)d_in[21];
    const float* mm    = (const float*)d_in[22];
    const float* vm    = (const float*)d_in[23];
    float* out = (float*)d_out;

    cudaFuncSetAttribute(k_pre,  cudaFuncAttributeMaxDynamicSharedMemorySize, KP_BYTES);
    cudaFuncSetAttribute(k_main, cudaFuncAttributeMaxDynamicSharedMemorySize, KM_BYTES);

    k_pre<<<512, 128, KP_BYTES>>>(x, w1, wr, gr, br, mr, vr,
                                  wm, bmap, gm, betam, mm, vm);
    k_main<<<dim3(128 / TW, 128 / TH, 4), 512, KM_BYTES>>>(
        ws, bs, g1, b1, m1, v1, w2, g2, b2, m2, v2, out);
}

// round 14
// speedup vs baseline: 1.7526x; 1.0103x over previous
#include <cuda_runtime.h>
#include <math.h>

#define EPS 1e-5f
typedef unsigned long long u64;

// ---------------- scratch (allocation forbidden -> __device__ globals) ----
__device__ float g_x1[4u * 64u * 128u * 128u];     // gelu(conv1(x))   16.8 MB
__device__ float g_skip[4u * 64u * 128u * 128u];   // bn(mapping(x))   16.8 MB
__device__ float g_r[4u * 16u * 128u * 128u];      // relu(bn(reduce))  4.2 MB

// ---------------- f32x2 helpers ----------------
__device__ __forceinline__ u64 pack2(float a, float b) {
    u64 r; asm("mov.b64 %0,{%1,%2};" : "=l"(r) : "f"(a), "f"(b)); return r;
}
__device__ __forceinline__ void unpack2(u64 v, float &a, float &b) {
    asm("mov.b64 {%0,%1},%2;" : "=f"(a), "=f"(b) : "l"(v));
}
__device__ __forceinline__ u64 fma2(u64 a, u64 b, u64 c) {
    u64 d; asm("fma.rn.f32x2 %0,%1,%2,%3;" : "=l"(d) : "l"(a), "l"(b), "l"(c)); return d;
}

// ---------------- fast exact-erf GELU (A&S 7.1.26, |erf err| < 1.5e-7) ----
__device__ __forceinline__ float gelu1(float v) {
    float ax = fabsf(v) * 0.70710678118654752440f;
    float d  = fmaf(0.3275911f, ax, 1.0f);
    float t; asm("rcp.approx.f32 %0,%1;" : "=f"(t) : "f"(d));
    float p = fmaf(1.061405429f, t, -1.453152027f);
    p = fmaf(p, t, 1.421413741f);
    p = fmaf(p, t, -0.284496736f);
    p = fmaf(p, t, 0.254829592f);
    p = p * t;
    float e = __expf(-ax * ax);
    float er = fmaf(-p, e, 1.0f);
    er = copysignf(er, v);
    return 0.5f * v * (1.0f + er);
}

// ===========================================================================
// Kernel 1 (R14): TWO THREADS per pixel (h = channel half), 256 thr/CTA,
// 3 CTAs/SM -> 24 warps/SM (was 12). f32x2 lanes = CHANNEL pairs.
//   x1 = gelu(w1@x); r = relu(bn(wr@x1)) via smem partial; skip = bn(wm@x+b)
// ===========================================================================
#define KP_W1N 0        // 2048  [ci][o]
#define KP_WMN 2048     // 2048  [ci][o] (bn folded)
#define KP_WRN 4096     // 1024  [c][j]
#define KP_TM  5120     // 64    skip bias (bn folded)
#define KP_SRV 5184     // 16
#define KP_TRV 5200     // 16
#define KP_RP  5216     // 2176  r-partial buffer [128 px][17]
#define KP_FLOATS 7392
#define KP_BYTES (KP_FLOATS * 4)

extern __shared__ __align__(16) float smem[];

__global__ void __launch_bounds__(256, 3) k_pre(
    const float* __restrict__ x,  const float* __restrict__ w1,
    const float* __restrict__ wr, const float* __restrict__ gr,
    const float* __restrict__ br, const float* __restrict__ mr,
    const float* __restrict__ vr, const float* __restrict__ wm,
    const float* __restrict__ bmap, const float* __restrict__ gm,
    const float* __restrict__ betam, const float* __restrict__ mm,
    const float* __restrict__ vm)
{
    float* w1n = smem + KP_W1N;
    float* wmn = smem + KP_WMN;
    float* wrn = smem + KP_WRN;
    float* tmv = smem + KP_TM;
    float* srv = smem + KP_SRV;
    float* trv = smem + KP_TRV;
    float* rbuf = smem + KP_RP;

    const int tid = threadIdx.x;
    for (int i = tid; i < 2048; i += 256) {
        int ci = i >> 6, o = i & 63;
        w1n[ci * 64 + o] = w1[o * 32 + ci];
        float s = gm[o] * rsqrtf(vm[o] + EPS);
        wmn[ci * 64 + o] = wm[o * 32 + ci] * s;
    }
    for (int i = tid; i < 1024; i += 256) {
        int c = i >> 4, j = i & 15;
        wrn[c * 16 + j] = wr[j * 64 + c];
    }
    if (tid < 64) {
        float s = gm[tid] * rsqrtf(vm[tid] + EPS);
        tmv[tid] = s * bmap[tid] + betam[tid] - mm[tid] * s;
    }
    if (tid < 16) {
        float s = gr[tid] * rsqrtf(vr[tid] + EPS);
        srv[tid] = s; trv[tid] = br[tid] - mr[tid] * s;
    }
    __syncthreads();

    const int p = tid & 127, h = tid >> 7;           // pixel-in-CTA, channel half
    const int pg = blockIdx.x * 128 + p;             // global pixel id
    const int b = pg >> 14, pix = pg & 16383;
    const float* xb = x + ((size_t)b << 19) + pix;

    float xv[32];
#pragma unroll
    for (int ci = 0; ci < 32; ci++) xv[ci] = __ldg(xb + ((size_t)ci << 14));

    // ---- conv1 (this thread's 32 outs, in 2 sub-blocks of 16) + gelu
    //      + r-partial over own 32 x1 channels ----
    u64 rp[8];
#pragma unroll
    for (int q = 0; q < 8; q++) rp[q] = 0ull;
    float* x1o = g_x1 + ((size_t)b << 20) + pix;
#pragma unroll
    for (int sub = 0; sub < 2; sub++) {
        const int base = h * 32 + sub * 16;          // first out channel
        u64 acc[8];
#pragma unroll
        for (int q = 0; q < 8; q++) acc[q] = 0ull;
#pragma unroll 4
        for (int ci = 0; ci < 32; ci++) {
            u64 xd = pack2(xv[ci], xv[ci]);
            const ulonglong2* wp = (const ulonglong2*)(w1n + ci * 64 + base);
#pragma unroll
            for (int q = 0; q < 4; q++) {
                ulonglong2 w = wp[q];
                acc[2 * q]     = fma2(w.x, xd, acc[2 * q]);
                acc[2 * q + 1] = fma2(w.y, xd, acc[2 * q + 1]);
            }
        }
#pragma unroll
        for (int lc = 0; lc < 8; lc++) {
            int c0 = base + 2 * lc;
            float v0, v1; unpack2(acc[lc], v0, v1);
            float g0 = gelu1(v0), g1 = gelu1(v1);
            x1o[(size_t)c0 << 14]       = g0;
            x1o[(size_t)(c0 + 1) << 14] = g1;
            u64 g0d = pack2(g0, g0), g1d = pack2(g1, g1);
            const ulonglong2* r0 = (const ulonglong2*)(wrn + c0 * 16);
            const ulonglong2* r1 = (const ulonglong2*)(wrn + (c0 + 1) * 16);
#pragma unroll
            for (int q = 0; q < 4; q++) {
                ulonglong2 wA = r0[q];
                rp[2 * q]     = fma2(wA.x, g0d, rp[2 * q]);
                rp[2 * q + 1] = fma2(wA.y, g0d, rp[2 * q + 1]);
                ulonglong2 wB = r1[q];
                rp[2 * q]     = fma2(wB.x, g1d, rp[2 * q]);
                rp[2 * q + 1] = fma2(wB.y, g1d, rp[2 * q + 1]);
            }
        }
    }
    // ---- combine r partials: h=1 stores, h=0 adds + bn + relu -> g_r ----
    if (h == 1) {
#pragma unroll
        for (int q = 0; q < 8; q++) {
            float a0, a1; unpack2(rp[q], a0, a1);
            rbuf[p * 17 + 2 * q]     = a0;
            rbuf[p * 17 + 2 * q + 1] = a1;
        }
    }
    __syncthreads();
    if (h == 0) {
        float* ro = g_r + (((size_t)b * 16) << 14) + pix;
#pragma unroll
        for (int q = 0; q < 8; q++) {
            float a0, a1; unpack2(rp[q], a0, a1);
            a0 += rbuf[p * 17 + 2 * q];
            a1 += rbuf[p * 17 + 2 * q + 1];
            ro[(size_t)(2 * q) << 14]     = fmaxf(fmaf(srv[2 * q],     a0, trv[2 * q]),     0.f);
            ro[(size_t)(2 * q + 1) << 14] = fmaxf(fmaf(srv[2 * q + 1], a1, trv[2 * q + 1]), 0.f);
        }
    }

    // ---- mapping skip (bn folded), this thread's 32 outs ----
    float* sko = g_skip + ((size_t)b << 20) + pix;
#pragma unroll
    for (int sub = 0; sub < 2; sub++) {
        const int base = h * 32 + sub * 16;
        u64 acc[8];
        const ulonglong2* tp = (const ulonglong2*)(tmv + base);
#pragma unroll
        for (int q = 0; q < 4; q++) { ulonglong2 t = tp[q]; acc[2 * q] = t.x; acc[2 * q + 1] = t.y; }
#pragma unroll 4
        for (int ci = 0; ci < 32; ci++) {
            u64 xd = pack2(xv[ci], xv[ci]);
            const ulonglong2* wp = (const ulonglong2*)(wmn + ci * 64 + base);
#pragma unroll
            for (int q = 0; q < 4; q++) {
                ulonglong2 w = wp[q];
                acc[2 * q]     = fma2(w.x, xd, acc[2 * q]);
                acc[2 * q + 1] = fma2(w.y, xd, acc[2 * q + 1]);
            }
        }
#pragma unroll
        for (int lc = 0; lc < 8; lc++) {
            int c0 = base + 2 * lc;
            float s0, s1; unpack2(acc[lc], s0, s1);
            sko[(size_t)c0 << 14]       = s0;
            sko[(size_t)(c0 + 1) << 14] = s1;
        }
    }
}

// ===========================================================================
// Kernel 2 (UNCHANGED from R13, passing): span-weight JIT + involution + BN1
// + GELU + conv2(BN2 folded) + skip + GELU. 2 CTAs/SM.
// ===========================================================================
#define TW 16
#define TH 8
#define HW 22
#define HP 308
#define CSTR 68
#define KM_X1S 0
#define KM_W2T (HP * CSTR)
#define KM_WSS (KM_W2T + 4096)
#define KM_S1V (KM_WSS + 3584)
#define KM_T1V (KM_S1V + 64)
#define KM_T2V (KM_T1V + 64)
#define KM_FLOATS (KM_T2V + 64)
#define KM_BYTES (KM_FLOATS * 4)

__global__ void __launch_bounds__(512, 2) k_main(
    const float* __restrict__ ws, const float* __restrict__ bs,
    const float* __restrict__ g1, const float* __restrict__ b1,
    const float* __restrict__ m1, const float* __restrict__ v1,
    const float* __restrict__ w2, const float* __restrict__ g2,
    const float* __restrict__ b2, const float* __restrict__ m2,
    const float* __restrict__ v2, float* __restrict__ out)
{
    float* x1s = smem + KM_X1S;
    float* w2t = smem + KM_W2T;
    float* wss = smem + KM_WSS;
    float* s1v = smem + KM_S1V;
    float* t1v = smem + KM_T1V;
    float* t2v = smem + KM_T2V;

    const int tid = threadIdx.x;
    const int b = blockIdx.z;
    const int tx0 = blockIdx.x * TW, ty0 = blockIdx.y * TH;

    for (int i = tid; i < 4096; i += 512) {
        int c = i >> 6, o = i & 63;
        float s2 = g2[o] * rsqrtf(v2[o] + EPS);
        w2t[c * 64 + o] = w2[o * 64 + c] * s2;
    }
    for (int i = tid; i < 3584; i += 512) {
        int dj = i & 7, j = (i >> 3) & 15, gd = i >> 7;
        int di = gd % 7, gq = gd / 7;
        wss[i] = (dj < 7) ? ws[(gq * 49 + di * 7 + dj) * 16 + j] : 0.f;
    }
    if (tid < 64) {
        float s1 = g1[tid] * rsqrtf(v1[tid] + EPS);
        s1v[tid] = s1; t1v[tid] = b1[tid] - m1[tid] * s1;
        float s2 = g2[tid] * rsqrtf(v2[tid] + EPS);
        t2v[tid] = b2[tid] - m2[tid] * s2;
    }

    const float* x1b = g_x1 + ((size_t)b << 20);
    for (int i = tid; i < HP * 64; i += 512) {
        int c = i / HP, hp = i - c * HP;
        int hy = hp / HW, hx = hp - hy * HW;
        int gy = ty0 - 3 + hy, gx = tx0 - 3 + hx;
        float v = 0.f;
        if (gy >= 0 && gy < 128 && gx >= 0 && gx < 128)
            v = __ldg(x1b + ((size_t)c << 14) + (gy << 7) + gx);
        x1s[hp * CSTR + c] = v;
    }
    __syncthreads();

    const int p = tid & 127, g = tid >> 7;
    const int py = p >> 4, px = p & 15;
    const int gy = ty0 + py, gx = tx0 + px;
    const int pix = (gy << 7) + gx;
    const int ch0 = g * 16;

    float r16[16];
    const float* rb = g_r + (((size_t)b * 16) << 14) + pix;
#pragma unroll
    for (int j = 0; j < 16; j++) r16[j] = __ldg(rb + ((size_t)j << 14));

    u64 acc[8];
#pragma unroll
    for (int q = 0; q < 8; q++) acc[q] = 0ull;
#pragma unroll
    for (int di = 0; di < 7; di++) {
        const float* bsp = bs + g * 49 + di * 7;
        u64 wa[4];
        wa[0] = pack2(__ldg(bsp + 0), __ldg(bsp + 1));
        wa[1] = pack2(__ldg(bsp + 2), __ldg(bsp + 3));
        wa[2] = pack2(__ldg(bsp + 4), __ldg(bsp + 5));
        wa[3] = pack2(__ldg(bsp + 6), 0.f);
        const ulonglong2* wsp = (const ulonglong2*)(wss + ((g * 7 + di) * 16) * 8);
#pragma unroll
        for (int j = 0; j < 16; j++) {
            u64 rd = pack2(r16[j], r16[j]);
            ulonglong2 wA = wsp[2 * j];
            ulonglong2 wB = wsp[2 * j + 1];
            wa[0] = fma2(wA.x, rd, wa[0]);
            wa[1] = fma2(wA.y, rd, wa[1]);
            wa[2] = fma2(wB.x, rd, wa[2]);
            wa[3] = fma2(wB.y, rd, wa[3]);
        }
        float w7[8];
        unpack2(wa[0], w7[0], w7[1]); unpack2(wa[1], w7[2], w7[3]);
        unpack2(wa[2], w7[4], w7[5]); unpack2(wa[3], w7[6], w7[7]);

        const float* rowb = x1s + ((py + di) * HW + px) * CSTR + ch0;
#pragma unroll
        for (int dj = 0; dj < 7; dj++) {
            u64 kp = pack2(w7[dj], w7[dj]);
            const ulonglong2* xp = (const ulonglong2*)(rowb + dj * CSTR);
#pragma unroll
            for (int q = 0; q < 4; q++) {
                ulonglong2 xv = xp[q];
                acc[2 * q]     = fma2(kp, xv.x, acc[2 * q]);
                acc[2 * q + 1] = fma2(kp, xv.y, acc[2 * q + 1]);
            }
        }
    }
    float y[16];
#pragma unroll
    for (int q = 0; q < 8; q++) {
        u64 s = *(const u64*)(s1v + ch0 + 2 * q);
        u64 t = *(const u64*)(t1v + ch0 + 2 * q);
        u64 v = fma2(acc[q], s, t);
        float a0, a1; unpack2(v, a0, a1);
        y[2 * q] = gelu1(a0); y[2 * q + 1] = gelu1(a1);
    }

    __syncthreads();
#pragma unroll
    for (int c = 0; c < 16; c++) x1s[p * CSTR + ch0 + c] = y[c];
    __syncthreads();

    u64 acc2[8];
#pragma unroll
    for (int q = 0; q < 8; q++) acc2[q] = *(const u64*)(t2v + ch0 + 2 * q);
    const float4* yb = (const float4*)(x1s + p * CSTR);
#pragma unroll 4
    for (int c4 = 0; c4 < 16; c4++) {
        float4 yv = yb[c4];
        float ya[4] = { yv.x, yv.y, yv.z, yv.w };
#pragma unroll
        for (int cc = 0; cc < 4; cc++) {
            int c = c4 * 4 + cc;
            u64 yp2 = pack2(ya[cc], ya[cc]);
            const ulonglong2* wp = (const ulonglong2*)(w2t + c * 64 + ch0);
#pragma unroll
            for (int q = 0; q < 4; q++) {
                ulonglong2 w = wp[q];
                acc2[2 * q]     = fma2(w.x, yp2, acc2[2 * q]);
                acc2[2 * q + 1] = fma2(w.y, yp2, acc2[2 * q + 1]);
            }
        }
    }
    const float* skb = g_skip + ((size_t)b << 20) + pix;
    float* ob = out + ((size_t)b << 20) + pix;
#pragma unroll
    for (int q = 0; q < 8; q++) {
        float a0, a1; unpack2(acc2[q], a0, a1);
        int o0 = ch0 + 2 * q;
        a0 += __ldg(skb + ((size_t)o0 << 14));
        a1 += __ldg(skb + ((size_t)(o0 + 1) << 14));
        ob[(size_t)o0 << 14]       = gelu1(a0);
        ob[(size_t)(o0 + 1) << 14] = gelu1(a1);
    }
}

// ===========================================================================
// Launch. Input order: x w1 wr gr br mr vr ws bs g1 b1 m1 v1
//                      w2 g2 b2 m2 v2 wm bmap gm betam mm vm
// ===========================================================================
extern "C" void kernel_launch(void* const* d_in, const int* in_sizes, int n_in,
                              void* d_out, int out_size)
{
    (void)in_sizes; (void)n_in; (void)out_size;
    const float* x     = (const float*)d_in[0];
    const float* w1    = (const float*)d_in[1];
    const float* wr    = (const float*)d_in[2];
    const float* gr    = (const float*)d_in[3];
    const float* br    = (const float*)d_in[4];
    const float* mr    = (const float*)d_in[5];
    const float* vr    = (const float*)d_in[6];
    const float* ws    = (const float*)d_in[7];
    const float* bs    = (const float*)d_in[8];
    const float* g1    = (const float*)d_in[9];
    const float* b1    = (const float*)d_in[10];
    const float* m1    = (const float*)d_in[11];
    const float* v1    = (const float*)d_in[12];
    const float* w2    = (const float*)d_in[13];
    const float* g2    = (const float*)d_in[14];
    const float* b2    = (const float*)d_in[15];
    const float* m2    = (const float*)d_in[16];
    const float* v2    = (const float*)d_in[17];
    const float* wm    = (const float*)d_in[18];
    const float* bmap  = (const float*)d_in[19];
    const float* gm    = (const float*)d_in[20];
    const float* betam = (const float*)d_in[21];
    const float* mm    = (const float*)d_in[22];
    const float* vm    = (const float*)d_in[23];
    float* out = (float*)d_out;

    cudaFuncSetAttribute(k_pre,  cudaFuncAttributeMaxDynamicSharedMemorySize, KP_BYTES);
    cudaFuncSetAttribute(k_main, cudaFuncAttributeMaxDynamicSharedMemorySize, KM_BYTES);

    k_pre<<<512, 256, KP_BYTES>>>(x, w1, wr, gr, br, mr, vr,
                                  wm, bmap, gm, betam, mm, vm);
    k_main<<<dim3(128 / TW, 128 / TH, 4), 512, KM_BYTES>>>(
        ws, bs, g1, b1, m1, v1, w2, g2, b2, m2, v2, out);
}